// round 3
// baseline (speedup 1.0000x reference)
#include <cuda_runtime.h>
#include <math.h>

#define EPSF 1e-6f
#define Bn 16
#define Tn 2048
#define LDn 256
#define NBn 32
#define BTn (Bn*Tn)
#define NCHUNK 64
#define CLEN 32

typedef unsigned long long ull;

__device__ __forceinline__ void ffma2(ull& d, ull a, ull b) {
    asm("fma.rn.f32x2 %0, %1, %2, %0;" : "+l"(d) : "l"(a), "l"(b));
}
__device__ __forceinline__ ull bc2(float x) {
    ull r; asm("mov.b64 %0, {%1, %1};" : "=l"(r) : "f"(x)); return r;
}
__device__ __forceinline__ float2 u2f(ull v) {
    float2 f; asm("mov.b64 {%0, %1}, %2;" : "=f"(f.x), "=f"(f.y) : "l"(v)); return f;
}

// -------- scratch (device globals: allocation-free) --------
__device__ float g_eA[(size_t)BTn*LDn];      // 32 MB: exp(A*t)
__device__ float g_inv[(size_t)BTn*LDn];     // 32 MB: 1/A
__device__ float g_aggA[Bn*NCHUNK*512];
__device__ float g_aggB[Bn*NCHUNK*512];
__device__ float g_carry[Bn*NCHUNK*512];
__device__ float g_Bt[LDn*LDn];              // B_w transposed: [d][e]
__device__ float g_WMEt[LDn*LDn];            // (M_w@E_w)^T : [d][f]
__device__ float g_WCEt[LDn*LDn];            // (C_w@E_w)^T : [d][f]
__device__ float g_WBCt[LDn*NBn];            // folded logit weights [d][n]
__device__ float g_Abasis[NBn*LDn];
__device__ float g_initmv[512];
__device__ float g_yvar[LDn];

// ---------------- precompute: vectors + A_basis ----------------
__global__ void k_pre_small(const float* __restrict__ E_w, const float* __restrict__ D,
                            const float* __restrict__ imp, const float* __restrict__ ilv,
                            const float* __restrict__ ylv) {
    const int tid = threadIdx.x;
    if (tid < 256) {
        float s = 0.f;
        for (int k = 0; k < 256; k++) s = fmaf(E_w[k*256 + tid], imp[k], s);
        g_initmv[tid] = s;
        g_yvar[tid] = expf(ylv[tid]) + EPSF;
    } else {
        const int i = tid - 256;
        float s = 0.f;
        for (int k = 0; k < 256; k++) {
            float e = E_w[k*256 + i];
            s = fmaf(e*e, expf(ilv[k]) + EPSF, s);
        }
        g_initmv[256 + i] = s;
    }
    for (int idx = tid; idx < NBn*LDn; idx += 512)
        g_Abasis[idx] = -(expf(D[idx]) + EPSF);
}

// ---------------- precompute: transpose B_w ----------------
__global__ void k_pre_transpose(const float* __restrict__ B_w) {
    __shared__ float t[32][33];
    const int tx = threadIdx.x, ty = threadIdx.y;
    const int e = blockIdx.y*32 + ty, d = blockIdx.x*32 + tx;
    t[ty][tx] = B_w[e*256 + d];
    __syncthreads();
    const int dd = blockIdx.x*32 + ty, ee = blockIdx.y*32 + tx;
    g_Bt[dd*256 + ee] = t[tx][ty];
}

// ---------------- precompute: W_ME^T, W_CE^T ----------------
__global__ void k_pre_gemm(const float* __restrict__ E_w, const float* __restrict__ M_w,
                           const float* __restrict__ C_w) {
    const float* X = (blockIdx.z == 0) ? M_w : C_w;
    float* out     = (blockIdx.z == 0) ? g_WMEt : g_WCEt;
    __shared__ float sE[32][33];
    __shared__ float sX[32][33];
    const int tx = threadIdx.x, ty = threadIdx.y;
    const int d0 = blockIdx.x*32, f0 = blockIdx.y*32;
    float acc = 0.f;
    for (int e0 = 0; e0 < 256; e0 += 32) {
        sE[ty][tx] = E_w[(e0+ty)*256 + d0 + tx];
        sX[ty][tx] = X[(f0+ty)*256 + e0 + tx];
        __syncthreads();
#pragma unroll
        for (int e = 0; e < 32; e++) acc = fmaf(sE[e][ty], sX[tx][e], acc);
        __syncthreads();
    }
    out[(d0+ty)*256 + f0 + tx] = acc;
}

// ---------------- precompute: folded logit weights ----------------
// g_WBCt[d][n] = sum_e B_w[e,d] * coeffW[n,e]
__global__ void k_pre_wbc(const float* __restrict__ B_w, const float* __restrict__ cW) {
    const int n = blockIdx.x;       // 32
    const int d = threadIdx.x;      // 256
    float s = 0.f;
#pragma unroll 4
    for (int e = 0; e < 256; e++)
        s = fmaf(B_w[e*256 + d], cW[n*256 + e], s);
    g_WBCt[d*32 + n] = s;
}

// ---------------- main per-token kernel ----------------
// 32 tokens/block = 1 scan chunk, 512 threads.
// alphas GEMM (f32x2) -> folded logits -> softmax -> A_mat -> exp + chunk aggregates
#define SMEM_TOKEN ((8704 + 8192 + 8192 + 1056 + 1056 + 32) * 4)
__global__ void __launch_bounds__(512, 2) k_token(const float* __restrict__ Z,
        const float* __restrict__ obs, const float* __restrict__ cb,
        float* __restrict__ alphas_out) {
    extern __shared__ float sm[];
    float* sZt   = sm;              // 256 x 34 : Z transposed [d][r]
    float* sAL   = sZt + 8704;      // 32 x 256 : alphas [r][c]
    float* sWB   = sAL + 8192;      // 32 x 256 : weight tile (later: partials)
    float* sLG   = sWB + 8192;      // 32 x 33  : logits
    float* sCoef = sLG + 1056;      // 32 x 33  : softmax coeffs
    float* sT    = sCoef + 1056;    // 32       : obs times

    const int tid = threadIdx.x;
    const int tok0 = blockIdx.x * 32;

    // ---- Z transposed load (coalesced read, strided smem write) ----
#pragma unroll
    for (int it = 0; it < 4; it++) {
        const int q = tid + it*512;           // float4 index (0..2047)
        const int r = q >> 6, cc = (q & 63) * 4;
        const float4 z4 = *(const float4*)(Z + (size_t)(tok0 + r)*256 + cc);
        sZt[(cc+0)*34 + r] = z4.x;
        sZt[(cc+1)*34 + r] = z4.y;
        sZt[(cc+2)*34 + r] = z4.z;
        sZt[(cc+3)*34 + r] = z4.w;
    }
    if (tid < 32) sT[tid] = obs[tok0 + tid];
    __syncthreads();

    const ull* pZ = (const ull*)sZt;          // [d][17] token pairs
    const int c4  = (tid & 63) * 4;
    const int rp0 = (tid >> 6) * 2;

    // ---- alphas GEMM: f32x2 along token pairs ----
    ull acc[2][4];
#pragma unroll
    for (int j = 0; j < 2; j++)
#pragma unroll
        for (int k = 0; k < 4; k++) acc[j][k] = 0ull;

    for (int dt = 0; dt < 8; dt++) {
#pragma unroll
        for (int it = 0; it < 4; it++) {
            const int q = tid + it*512;
            ((float4*)sWB)[q] = ((const float4*)(g_Bt + dt*8192))[q];
        }
        __syncthreads();
#pragma unroll 2
        for (int dd = 0; dd < 32; dd++) {
            const int d = dt*32 + dd;
            const float4 w4 = *(const float4*)(sWB + dd*256 + c4);
            const ull w0 = bc2(w4.x), w1 = bc2(w4.y), w2 = bc2(w4.z), w3 = bc2(w4.w);
            const ull x0 = pZ[d*17 + rp0], x1 = pZ[d*17 + rp0 + 1];
            ffma2(acc[0][0], x0, w0); ffma2(acc[0][1], x0, w1);
            ffma2(acc[0][2], x0, w2); ffma2(acc[0][3], x0, w3);
            ffma2(acc[1][0], x1, w0); ffma2(acc[1][1], x1, w1);
            ffma2(acc[1][2], x1, w2); ffma2(acc[1][3], x1, w3);
        }
        __syncthreads();
    }
    // epilogue: alphas -> smem + global
#pragma unroll
    for (int j = 0; j < 2; j++) {
        const int r0 = 2*(rp0 + j);
        const float2 a0 = u2f(acc[j][0]), a1 = u2f(acc[j][1]);
        const float2 a2 = u2f(acc[j][2]), a3 = u2f(acc[j][3]);
        const float4 lo = make_float4(a0.x, a1.x, a2.x, a3.x);
        const float4 hi = make_float4(a0.y, a1.y, a2.y, a3.y);
        *(float4*)(sAL + r0*256 + c4)     = lo;
        *(float4*)(sAL + (r0+1)*256 + c4) = hi;
        *(float4*)(alphas_out + (size_t)(tok0+r0)*256 + c4)   = lo;
        *(float4*)(alphas_out + (size_t)(tok0+r0+1)*256 + c4) = hi;
    }

    // ---- folded logits: logits[t][n] = Z[t,:] . WBC[:,n] ----
    {
        const int rpl = tid & 15;
        const int nn  = tid >> 4;     // 0..31
        ull accL = 0ull;
#pragma unroll 4
        for (int d = 0; d < 256; d++)
            ffma2(accL, pZ[d*17 + rpl], bc2(g_WBCt[d*32 + nn]));
        const float bias = cb[nn];
        const float2 lg = u2f(accL);
        sLG[(2*rpl)*33   + nn] = lg.x + bias;
        sLG[(2*rpl+1)*33 + nn] = lg.y + bias;
    }
    __syncthreads();

    // ---- softmax: 16 warps x 2 tokens, lane = basis ----
    {
        const int lane = tid & 31, warp = tid >> 5;
#pragma unroll
        for (int rr = 0; rr < 2; rr++) {
            const int r = warp*2 + rr;
            const float lg = sLG[r*33 + lane];
            float m = lg;
#pragma unroll
            for (int off = 16; off > 0; off >>= 1)
                m = fmaxf(m, __shfl_xor_sync(0xffffffffu, m, off));
            const float e = __expf(lg - m);
            float s = e;
#pragma unroll
            for (int off = 16; off > 0; off >>= 1)
                s += __shfl_xor_sync(0xffffffffu, s, off);
            sCoef[r*33 + lane] = e / s;
        }
    }
    __syncthreads();

    // ---- A_mat + exp terms + half-chunk aggregates ----
    const int c = tid & 255;
    const int h = tid >> 8;
    const int rbase = h * 16;
    float am[16];
#pragma unroll
    for (int rr = 0; rr < 16; rr++) am[rr] = 0.f;
#pragma unroll 4
    for (int n = 0; n < 32; n++) {
        const float ab = g_Abasis[n*256 + c];
#pragma unroll
        for (int rr = 0; rr < 16; rr++)
            am[rr] = fmaf(sCoef[(rbase+rr)*33 + n], ab, am[rr]);
    }
    float aAm = 1.f, bBm = 0.f, aAv = 1.f, bBv = 0.f;
#pragma unroll 4
    for (int rr = 0; rr < 16; rr++) {
        const int r = rbase + rr;
        const float a = am[rr];
        const float t = sT[r];
        const float eAm = __expf(a * t);
        const float inv = __fdividef(1.0f, a);
        const float al  = sAL[r*256 + c];
        const float eBm = (eAm - 1.f) * inv * al;
        const float eAv = eAm * eAm;
        const float eBv = 0.5f*(eAv - 1.f)*inv + EPSF;
        const size_t o = (size_t)(tok0 + r)*256 + c;
        g_eA[o]  = eAm;
        g_inv[o] = inv;
        bBm = fmaf(eAm, bBm, eBm); aAm *= eAm;
        bBv = fmaf(eAv, bBv, eBv); aAv *= eAv;
    }
    // combine the two 16-token halves: A=A1*A0, B=B1+A1*B0
    float* sPar = sWB;   // reuse weight-staging area
    sPar[(h*4+0)*256 + c] = aAm;
    sPar[(h*4+1)*256 + c] = bBm;
    sPar[(h*4+2)*256 + c] = aAv;
    sPar[(h*4+3)*256 + c] = bBv;
    __syncthreads();
    if (tid < 256) {
        const int bc = blockIdx.x;
        const float A0m = sPar[tid],          B0m = sPar[256 + tid];
        const float A0v = sPar[512 + tid],    B0v = sPar[768 + tid];
        const float A1m = sPar[1024 + tid],   B1m = sPar[1280 + tid];
        const float A1v = sPar[1536 + tid],   B1v = sPar[1792 + tid];
        g_aggA[bc*512 + tid]       = A1m * A0m;
        g_aggB[bc*512 + tid]       = fmaf(A1m, B0m, B1m);
        g_aggA[bc*512 + 256 + tid] = A1v * A0v;
        g_aggB[bc*512 + 256 + tid] = fmaf(A1v, B0v, B1v);
    }
}

// ---------------- scan over chunk aggregates ----------------
__global__ void k_scan2() {
    const int b = blockIdx.x;
    const int c = threadIdx.x;
    float s = g_initmv[c];
#pragma unroll 4
    for (int j = 0; j < NCHUNK; j++) {
        const int idx = (b*NCHUNK + j)*512 + c;
        g_carry[idx] = s;
        s = fmaf(g_aggA[idx], s, g_aggB[idx]);
    }
}

// ---------------- fused scan-apply + output GEMMs ----------------
// 32 tokens/block (= 1 chunk), 512 threads.
#define SMEM_FUSED ((8704*3 + 8192*2) * 4)
__global__ void __launch_bounds__(512, 1) k_fused(const float* __restrict__ Z,
        const float* __restrict__ alphas,
        float* __restrict__ out_means, float* __restrict__ out_stds) {
    extern __shared__ float sm[];
    float* sXt = sm;            // 256 x 34 mean-state [d][r]
    float* sVt = sXt + 8704;    // 256 x 34 sqrt(var+yvar)
    float* sHt = sVt + 8704;    // 256 x 34 Z
    float* sWM = sHt + 8704;    // 32 x 256
    float* sWC = sWM + 8192;    // 32 x 256

    const int tid  = threadIdx.x;
    const int bc   = blockIdx.x;
    const int tok0 = bc * 32;

    // ---- phase 1: apply carry, build transposed activation tiles ----
    {
        const int c = tid & 255;
        if ((tid >> 8) == 0) {
            float s = g_carry[bc*512 + c];
#pragma unroll 4
            for (int r = 0; r < 32; r++) {
                const size_t o = (size_t)(tok0 + r)*256 + c;
                const float eAm = g_eA[o], inv = g_inv[o], al = alphas[o];
                const float bm = (eAm - 1.f) * inv * al;
                s = fmaf(eAm, s, bm);
                sXt[c*34 + r] = s;
                sHt[c*34 + r] = Z[o];
            }
        } else {
            float s = g_carry[bc*512 + 256 + c];
            const float yv = g_yvar[c];
#pragma unroll 4
            for (int r = 0; r < 32; r++) {
                const size_t o = (size_t)(tok0 + r)*256 + c;
                const float eAm = g_eA[o], inv = g_inv[o];
                const float eAv = eAm * eAm;
                const float bv = 0.5f*(eAv - 1.f)*inv + EPSF;
                s = fmaf(eAv, s, bv);
                sVt[c*34 + r] = sqrtf(s + yv);
            }
        }
    }
    __syncthreads();

    // ---- phase 2: f32x2 GEMMs ----
    const ull* pX = (const ull*)sXt;
    const ull* pV = (const ull*)sVt;
    const ull* pH = (const ull*)sHt;
    const int c4  = (tid & 63) * 4;
    const int rp0 = (tid >> 6) * 2;
    ull accM[2][4], accS[2][4];
#pragma unroll
    for (int j = 0; j < 2; j++)
#pragma unroll
        for (int k = 0; k < 4; k++) { accM[j][k] = 0ull; accS[j][k] = 0ull; }

    for (int dt = 0; dt < 8; dt++) {
#pragma unroll
        for (int it = 0; it < 4; it++) {
            const int q = tid + it*512;
            ((float4*)sWM)[q] = ((const float4*)(g_WMEt + dt*8192))[q];
            ((float4*)sWC)[q] = ((const float4*)(g_WCEt + dt*8192))[q];
        }
        __syncthreads();
#pragma unroll 2
        for (int dd = 0; dd < 32; dd++) {
            const int d = dt*32 + dd;
            const float4 wm4 = *(const float4*)(sWM + dd*256 + c4);
            const float4 wc4 = *(const float4*)(sWC + dd*256 + c4);
            const ull wm0 = bc2(wm4.x), wm1 = bc2(wm4.y), wm2 = bc2(wm4.z), wm3 = bc2(wm4.w);
            const ull wc0 = bc2(wc4.x), wc1 = bc2(wc4.y), wc2 = bc2(wc4.z), wc3 = bc2(wc4.w);
            const ull xm0 = pX[d*17 + rp0], xm1 = pX[d*17 + rp0 + 1];
            const ull xv0 = pV[d*17 + rp0], xv1 = pV[d*17 + rp0 + 1];
            const ull xh0 = pH[d*17 + rp0], xh1 = pH[d*17 + rp0 + 1];
            ffma2(accM[0][0], xm0, wm0); ffma2(accM[0][1], xm0, wm1);
            ffma2(accM[0][2], xm0, wm2); ffma2(accM[0][3], xm0, wm3);
            ffma2(accM[0][0], xh0, wc0); ffma2(accM[0][1], xh0, wc1);
            ffma2(accM[0][2], xh0, wc2); ffma2(accM[0][3], xh0, wc3);
            ffma2(accS[0][0], xv0, wm0); ffma2(accS[0][1], xv0, wm1);
            ffma2(accS[0][2], xv0, wm2); ffma2(accS[0][3], xv0, wm3);
            ffma2(accM[1][0], xm1, wm0); ffma2(accM[1][1], xm1, wm1);
            ffma2(accM[1][2], xm1, wm2); ffma2(accM[1][3], xm1, wm3);
            ffma2(accM[1][0], xh1, wc0); ffma2(accM[1][1], xh1, wc1);
            ffma2(accM[1][2], xh1, wc2); ffma2(accM[1][3], xh1, wc3);
            ffma2(accS[1][0], xv1, wm0); ffma2(accS[1][1], xv1, wm1);
            ffma2(accS[1][2], xv1, wm2); ffma2(accS[1][3], xv1, wm3);
        }
        __syncthreads();
    }

    // ---- epilogue: float4 stores ----
#pragma unroll
    for (int j = 0; j < 2; j++) {
        const int r0 = 2*(rp0 + j);
        const float2 m0 = u2f(accM[j][0]), m1 = u2f(accM[j][1]);
        const float2 m2 = u2f(accM[j][2]), m3 = u2f(accM[j][3]);
        const float2 s0 = u2f(accS[j][0]), s1 = u2f(accS[j][1]);
        const float2 s2 = u2f(accS[j][2]), s3 = u2f(accS[j][3]);
        *(float4*)(out_means + (size_t)(tok0+r0)*256 + c4)   = make_float4(m0.x, m1.x, m2.x, m3.x);
        *(float4*)(out_means + (size_t)(tok0+r0+1)*256 + c4) = make_float4(m0.y, m1.y, m2.y, m3.y);
        *(float4*)(out_stds  + (size_t)(tok0+r0)*256 + c4)   = make_float4(s0.x, s1.x, s2.x, s3.x);
        *(float4*)(out_stds  + (size_t)(tok0+r0+1)*256 + c4) = make_float4(s0.y, s1.y, s2.y, s3.y);
    }
}

// ---------------- launch ----------------
extern "C" void kernel_launch(void* const* d_in, const int* in_sizes, int n_in,
                              void* d_out, int out_size) {
    const float* Z   = (const float*)d_in[0];
    const float* obs = (const float*)d_in[1];
    const float* D   = (const float*)d_in[2];
    const float* cW  = (const float*)d_in[3];
    const float* cb  = (const float*)d_in[4];
    const float* E_w = (const float*)d_in[5];
    const float* B_w = (const float*)d_in[6];
    const float* C_w = (const float*)d_in[7];
    const float* M_w = (const float*)d_in[8];
    const float* imp = (const float*)d_in[9];
    const float* ilv = (const float*)d_in[10];
    const float* ylv = (const float*)d_in[11];

    float* out        = (float*)d_out;
    float* out_means  = out;
    float* out_stds   = out + (size_t)BTn * LDn;
    float* out_alphas = out + 2 * (size_t)BTn * LDn;

    cudaFuncSetAttribute(k_token, cudaFuncAttributeMaxDynamicSharedMemorySize, SMEM_TOKEN);
    cudaFuncSetAttribute(k_fused, cudaFuncAttributeMaxDynamicSharedMemorySize, SMEM_FUSED);

    k_pre_small<<<1, 512>>>(E_w, D, imp, ilv, ylv);
    k_pre_transpose<<<dim3(8,8), dim3(32,32)>>>(B_w);
    k_pre_gemm<<<dim3(8,8,2), dim3(32,32)>>>(E_w, M_w, C_w);
    k_pre_wbc<<<NBn, 256>>>(B_w, cW);
    k_token<<<BTn/32, 512, SMEM_TOKEN>>>(Z, obs, cb, out_alphas);
    k_scan2<<<Bn, 512>>>();
    k_fused<<<BTn/32, 512, SMEM_FUSED>>>(Z, out_alphas, out_means, out_stds);
}

// round 8
// speedup vs baseline: 1.3097x; 1.3097x over previous
#include <cuda_runtime.h>
#include <cuda_bf16.h>
#include <math.h>
#include <stdint.h>

#define EPSF 1e-6f
#define Bn 16
#define Tn 2048
#define LDn 256
#define NBn 32
#define BTn (Bn*Tn)
#define NCHUNK 64

typedef unsigned long long ull;

// ---------- f32x2 helpers (k_token) ----------
__device__ __forceinline__ void ffma2(ull& d, ull a, ull b) {
    asm("fma.rn.f32x2 %0, %1, %2, %0;" : "+l"(d) : "l"(a), "l"(b));
}
__device__ __forceinline__ ull bc2(float x) {
    ull r; asm("mov.b64 %0, {%1, %1};" : "=l"(r) : "f"(x)); return r;
}
__device__ __forceinline__ float2 u2f(ull v) {
    float2 f; asm("mov.b64 {%0, %1}, %2;" : "=f"(f.x), "=f"(f.y) : "l"(v)); return f;
}

// ---------- warp-mma helpers (baseline PTX, valid on compute_103) ----------
static __device__ __forceinline__ uint32_t smem_u32(const void* p) {
    uint32_t a;
    asm("{ .reg .u64 t; cvta.to.shared.u64 t, %1; cvt.u32.u64 %0, t; }" : "=r"(a) : "l"(p));
    return a;
}
__device__ __forceinline__ void ldsm4(uint32_t addr, uint32_t& r0, uint32_t& r1,
                                      uint32_t& r2, uint32_t& r3) {
    asm volatile("ldmatrix.sync.aligned.m8n8.x4.shared.b16 {%0,%1,%2,%3}, [%4];"
                 : "=r"(r0), "=r"(r1), "=r"(r2), "=r"(r3) : "r"(addr));
}
__device__ __forceinline__ void mma_bf16(float* c, const uint32_t* a, uint32_t b0, uint32_t b1) {
    asm volatile(
        "mma.sync.aligned.m16n8k16.row.col.f32.bf16.bf16.f32 "
        "{%0,%1,%2,%3},{%4,%5,%6,%7},{%8,%9},{%0,%1,%2,%3};"
        : "+f"(c[0]), "+f"(c[1]), "+f"(c[2]), "+f"(c[3])
        : "r"(a[0]), "r"(a[1]), "r"(a[2]), "r"(a[3]), "r"(b0), "r"(b1));
}

// -------- scratch (device globals) --------
__device__ float g_eA[(size_t)BTn*LDn];
__device__ float g_inv[(size_t)BTn*LDn];
__device__ float g_aggA[Bn*NCHUNK*512];
__device__ float g_aggB[Bn*NCHUNK*512];
__device__ float g_carry[Bn*NCHUNK*512];
__device__ float g_Bt[LDn*LDn];
__device__ float g_WBCt[LDn*NBn];
__device__ float g_Abasis[NBn*LDn];
__device__ float g_initmv[512];
__device__ float g_yvar[LDn];
// bf16 split weights, layout [kchunk(8)][f(256)][k(32)] per matrix
__device__ __align__(16) __nv_bfloat16 g_WMEh[65536];
__device__ __align__(16) __nv_bfloat16 g_WMEl[65536];
__device__ __align__(16) __nv_bfloat16 g_WCEh[65536];
__device__ __align__(16) __nv_bfloat16 g_WCEl[65536];

// ---------------- precompute: vectors (warp-per-output) + A_basis ----------------
__global__ void k_pre_vec(const float* __restrict__ E_w, const float* __restrict__ D,
                          const float* __restrict__ imp, const float* __restrict__ ilv,
                          const float* __restrict__ ylv) {
    const int tid = threadIdx.x, lane = tid & 31;
    const int w = blockIdx.x*8 + (tid >> 5);
    float s = 0.f;
    if (w < 256) {
#pragma unroll
        for (int j = 0; j < 8; j++) { int k = lane + 32*j; s = fmaf(E_w[k*256 + w], imp[k], s); }
    } else {
        const int i = w - 256;
#pragma unroll
        for (int j = 0; j < 8; j++) {
            int k = lane + 32*j; float e = E_w[k*256 + i];
            s = fmaf(e*e, expf(ilv[k]) + EPSF, s);
        }
    }
#pragma unroll
    for (int off = 16; off > 0; off >>= 1) s += __shfl_xor_sync(0xffffffffu, s, off);
    if (lane == 0) {
        g_initmv[w] = s;
        if (w < 256) g_yvar[w] = expf(ylv[w]) + EPSF;
    }
    const int gid = blockIdx.x*256 + tid;
    if (gid < NBn*LDn) g_Abasis[gid] = -(expf(D[gid]) + EPSF);
}

// ---------------- precompute: transpose B_w ----------------
__global__ void k_pre_transpose(const float* __restrict__ B_w) {
    __shared__ float t[32][33];
    const int tx = threadIdx.x, ty = threadIdx.y;
    t[ty][tx] = B_w[(blockIdx.y*32 + ty)*256 + blockIdx.x*32 + tx];
    __syncthreads();
    g_Bt[(blockIdx.x*32 + ty)*256 + blockIdx.y*32 + tx] = t[tx][ty];
}

// ---------------- precompute: folded logit weights ----------------
__global__ void k_pre_wbc(const float* __restrict__ B_w, const float* __restrict__ cW) {
    const int lane = threadIdx.x & 31;
    const int idx = blockIdx.x*8 + (threadIdx.x >> 5);
    const int d = idx & 255, n = idx >> 8;
    float s = 0.f;
#pragma unroll
    for (int j = 0; j < 8; j++) {
        int e = lane + 32*j;
        s = fmaf(B_w[e*256 + d], cW[n*256 + e], s);
    }
#pragma unroll
    for (int off = 16; off > 0; off >>= 1) s += __shfl_xor_sync(0xffffffffu, s, off);
    if (lane == 0) g_WBCt[d*32 + n] = s;
}

// ---------------- precompute: W_ME/W_CE bf16 splits, [kc][f][kk] ----------------
__global__ void k_pre_gemm(const float* __restrict__ E_w, const float* __restrict__ M_w,
                           const float* __restrict__ C_w) {
    const float* X = (blockIdx.z == 0) ? M_w : C_w;
    __nv_bfloat16* oh = (blockIdx.z == 0) ? g_WMEh : g_WCEh;
    __nv_bfloat16* ol = (blockIdx.z == 0) ? g_WMEl : g_WCEl;
    __shared__ float sE[32][33];
    __shared__ float sX[32][33];
    const int tx = threadIdx.x, ty = threadIdx.y;
    const int d0 = blockIdx.x*32, f0 = blockIdx.y*32;
    float acc = 0.f;
    for (int e0 = 0; e0 < 256; e0 += 32) {
        sE[ty][tx] = E_w[(e0+ty)*256 + d0 + tx];
        sX[ty][tx] = X[(f0+ty)*256 + e0 + tx];
        __syncthreads();
#pragma unroll
        for (int e = 0; e < 32; e++) acc = fmaf(sE[e][ty], sX[tx][e], acc);
        __syncthreads();
    }
    const int f = f0 + tx, d = d0 + ty;     // d = k dim, f = output dim
    __nv_bfloat16 h = __float2bfloat16(acc);
    __nv_bfloat16 l = __float2bfloat16(acc - __bfloat162float(h));
    const int idx = (d >> 5)*8192 + f*32 + (d & 31);
    oh[idx] = h;
    ol[idx] = l;
}

// ---------------- k_token (proven R2 version) ----------------
#define SMEM_TOKEN ((8704 + 8192 + 8192 + 1056 + 1056 + 32) * 4)
__global__ void __launch_bounds__(512, 2) k_token(const float* __restrict__ Z,
        const float* __restrict__ obs, const float* __restrict__ cb,
        float* __restrict__ alphas_out) {
    extern __shared__ float sm[];
    float* sZt   = sm;
    float* sAL   = sZt + 8704;
    float* sWB   = sAL + 8192;
    float* sLG   = sWB + 8192;
    float* sCoef = sLG + 1056;
    float* sT    = sCoef + 1056;
    const int tid = threadIdx.x;
    const int tok0 = blockIdx.x * 32;
#pragma unroll
    for (int it = 0; it < 4; it++) {
        const int q = tid + it*512;
        const int r = q >> 6, cc = (q & 63) * 4;
        const float4 z4 = *(const float4*)(Z + (size_t)(tok0 + r)*256 + cc);
        sZt[(cc+0)*34 + r] = z4.x; sZt[(cc+1)*34 + r] = z4.y;
        sZt[(cc+2)*34 + r] = z4.z; sZt[(cc+3)*34 + r] = z4.w;
    }
    if (tid < 32) sT[tid] = obs[tok0 + tid];
    __syncthreads();
    const ull* pZ = (const ull*)sZt;
    const int c4  = (tid & 63) * 4;
    const int rp0 = (tid >> 6) * 2;
    ull acc[2][4];
#pragma unroll
    for (int j = 0; j < 2; j++)
#pragma unroll
        for (int k = 0; k < 4; k++) acc[j][k] = 0ull;
    for (int dt = 0; dt < 8; dt++) {
#pragma unroll
        for (int it = 0; it < 4; it++) {
            const int q = tid + it*512;
            ((float4*)sWB)[q] = ((const float4*)(g_Bt + dt*8192))[q];
        }
        __syncthreads();
#pragma unroll 2
        for (int dd = 0; dd < 32; dd++) {
            const int d = dt*32 + dd;
            const float4 w4 = *(const float4*)(sWB + dd*256 + c4);
            const ull w0 = bc2(w4.x), w1 = bc2(w4.y), w2 = bc2(w4.z), w3 = bc2(w4.w);
            const ull x0 = pZ[d*17 + rp0], x1 = pZ[d*17 + rp0 + 1];
            ffma2(acc[0][0], x0, w0); ffma2(acc[0][1], x0, w1);
            ffma2(acc[0][2], x0, w2); ffma2(acc[0][3], x0, w3);
            ffma2(acc[1][0], x1, w0); ffma2(acc[1][1], x1, w1);
            ffma2(acc[1][2], x1, w2); ffma2(acc[1][3], x1, w3);
        }
        __syncthreads();
    }
#pragma unroll
    for (int j = 0; j < 2; j++) {
        const int r0 = 2*(rp0 + j);
        const float2 a0 = u2f(acc[j][0]), a1 = u2f(acc[j][1]);
        const float2 a2 = u2f(acc[j][2]), a3 = u2f(acc[j][3]);
        const float4 lo = make_float4(a0.x, a1.x, a2.x, a3.x);
        const float4 hi = make_float4(a0.y, a1.y, a2.y, a3.y);
        *(float4*)(sAL + r0*256 + c4)     = lo;
        *(float4*)(sAL + (r0+1)*256 + c4) = hi;
        *(float4*)(alphas_out + (size_t)(tok0+r0)*256 + c4)   = lo;
        *(float4*)(alphas_out + (size_t)(tok0+r0+1)*256 + c4) = hi;
    }
    {
        const int rpl = tid & 15;
        const int nn  = tid >> 4;
        ull accL = 0ull;
#pragma unroll 4
        for (int d = 0; d < 256; d++)
            ffma2(accL, pZ[d*17 + rpl], bc2(g_WBCt[d*32 + nn]));
        const float bias = cb[nn];
        const float2 lg = u2f(accL);
        sLG[(2*rpl)*33   + nn] = lg.x + bias;
        sLG[(2*rpl+1)*33 + nn] = lg.y + bias;
    }
    __syncthreads();
    {
        const int lane = tid & 31, warp = tid >> 5;
#pragma unroll
        for (int rr = 0; rr < 2; rr++) {
            const int r = warp*2 + rr;
            const float lg = sLG[r*33 + lane];
            float m = lg;
#pragma unroll
            for (int off = 16; off > 0; off >>= 1)
                m = fmaxf(m, __shfl_xor_sync(0xffffffffu, m, off));
            const float e = __expf(lg - m);
            float s = e;
#pragma unroll
            for (int off = 16; off > 0; off >>= 1)
                s += __shfl_xor_sync(0xffffffffu, s, off);
            sCoef[r*33 + lane] = e / s;
        }
    }
    __syncthreads();
    const int c = tid & 255;
    const int h = tid >> 8;
    const int rbase = h * 16;
    float am[16];
#pragma unroll
    for (int rr = 0; rr < 16; rr++) am[rr] = 0.f;
#pragma unroll 4
    for (int n = 0; n < 32; n++) {
        const float ab = g_Abasis[n*256 + c];
#pragma unroll
        for (int rr = 0; rr < 16; rr++)
            am[rr] = fmaf(sCoef[(rbase+rr)*33 + n], ab, am[rr]);
    }
    float aAm = 1.f, bBm = 0.f, aAv = 1.f, bBv = 0.f;
#pragma unroll 4
    for (int rr = 0; rr < 16; rr++) {
        const int r = rbase + rr;
        const float a = am[rr];
        const float t = sT[r];
        const float eAm = __expf(a * t);
        const float inv = __fdividef(1.0f, a);
        const float al  = sAL[r*256 + c];
        const float eBm = (eAm - 1.f) * inv * al;
        const float eAv = eAm * eAm;
        const float eBv = 0.5f*(eAv - 1.f)*inv + EPSF;
        const size_t o = (size_t)(tok0 + r)*256 + c;
        g_eA[o]  = eAm;
        g_inv[o] = inv;
        bBm = fmaf(eAm, bBm, eBm); aAm *= eAm;
        bBv = fmaf(eAv, bBv, eBv); aAv *= eAv;
    }
    float* sPar = sWB;
    sPar[(h*4+0)*256 + c] = aAm;
    sPar[(h*4+1)*256 + c] = bBm;
    sPar[(h*4+2)*256 + c] = aAv;
    sPar[(h*4+3)*256 + c] = bBv;
    __syncthreads();
    if (tid < 256) {
        const int bc = blockIdx.x;
        const float A0m = sPar[tid],        B0m = sPar[256 + tid];
        const float A0v = sPar[512 + tid],  B0v = sPar[768 + tid];
        const float A1m = sPar[1024 + tid], B1m = sPar[1280 + tid];
        const float A1v = sPar[1536 + tid], B1v = sPar[1792 + tid];
        g_aggA[bc*512 + tid]       = A1m * A0m;
        g_aggB[bc*512 + tid]       = fmaf(A1m, B0m, B1m);
        g_aggA[bc*512 + 256 + tid] = A1v * A0v;
        g_aggB[bc*512 + 256 + tid] = fmaf(A1v, B0v, B1v);
    }
}

// ---------------- scan over chunk aggregates ----------------
__global__ void k_scan2() {
    const int b = blockIdx.x;
    const int c = threadIdx.x;
    float s = g_initmv[c];
#pragma unroll 4
    for (int j = 0; j < NCHUNK; j++) {
        const int idx = (b*NCHUNK + j)*512 + c;
        g_carry[idx] = s;
        s = fmaf(g_aggA[idx], s, g_aggB[idx]);
    }
}

// ---------------- k_fused: scan-apply + warp-mma output GEMMs ----------------
// A tiles: 6 x (32 rows x 264 bf16), stride 528B (16B-aligned).
// B tiles: 4 x (256 x 40 bf16), stride 80B (16B-aligned, conflict-free mod 128).
#define ASTRIDE 528
#define ATILE   16896
#define BSTRIDE 80
#define BTILE   20480
#define BBASE   (6*ATILE)
#define SMEM_OUT (BBASE + 4*BTILE)

__device__ __forceinline__ void put_split(char* hB, char* lB, int r, int d, float v) {
    __nv_bfloat16 h = __float2bfloat16(v);
    __nv_bfloat16 l = __float2bfloat16(v - __bfloat162float(h));
    const uint32_t off = (uint32_t)r*ASTRIDE + (uint32_t)d*2;
    *(__nv_bfloat16*)(hB + off) = h;
    *(__nv_bfloat16*)(lB + off) = l;
}

__global__ void __launch_bounds__(512, 1) k_fused(const float* __restrict__ Z,
        const float* __restrict__ alphas,
        float* __restrict__ out_means, float* __restrict__ out_stds) {
    extern __shared__ char smc[];
    const uint32_t sbase = smem_u32(smc);
    const int tid = threadIdx.x;
    const int bc = blockIdx.x;
    const int tok0 = bc * 32;

    // ---- phase 1: scan apply -> bf16 split tiles ----
    {
        const int d = tid & 255;
        if (tid < 256) {
            float s = g_carry[bc*512 + d];
#pragma unroll 4
            for (int r = 0; r < 32; r++) {
                const size_t o = (size_t)(tok0 + r)*256 + d;
                const float eA = g_eA[o], iv = g_inv[o], al = alphas[o];
                s = fmaf(eA, s, (eA - 1.f)*iv*al);
                put_split(smc, smc + ATILE, r, d, s);                    // xm
                put_split(smc + 2*ATILE, smc + 3*ATILE, r, d, Z[o]);     // h
            }
        } else {
            float s = g_carry[bc*512 + 256 + d];
            const float yv = g_yvar[d];
#pragma unroll 4
            for (int r = 0; r < 32; r++) {
                const size_t o = (size_t)(tok0 + r)*256 + d;
                const float eA = g_eA[o], iv = g_inv[o];
                const float eAv = eA * eA;
                s = fmaf(eAv, s, 0.5f*(eAv - 1.f)*iv + EPSF);
                put_split(smc + 4*ATILE, smc + 5*ATILE, r, d, sqrtf(s + yv));  // v
            }
        }
    }

    // ---- phase 2: warp mma ----
    const int lane = tid & 31, wid = tid >> 5;
    const int row0 = (wid & 1) * 16;
    const int col0 = (wid >> 1) * 32;
    float cm[4][4], cs[4][4];
#pragma unroll
    for (int nt = 0; nt < 4; nt++)
#pragma unroll
        for (int q = 0; q < 4; q++) { cm[nt][q] = 0.f; cs[nt][q] = 0.f; }

    const uint32_t aoff = sbase + (uint32_t)(row0 + (lane & 15))*ASTRIDE + (uint32_t)(lane >> 4)*16;
    const uint32_t boff = sbase + BBASE + (uint32_t)(col0 + (lane & 15))*BSTRIDE + (uint32_t)(lane >> 4)*16;
    const uint4* gB[4] = { (const uint4*)g_WMEh, (const uint4*)g_WMEl,
                           (const uint4*)g_WCEh, (const uint4*)g_WCEl };

    for (int kc = 0; kc < 8; kc++) {
        __syncthreads();
        // stage B: per matrix per kc chunk = 256 f x 32 k bf16 = 1024 uint4
#pragma unroll
        for (int m = 0; m < 4; m++) {
            const uint4* src = gB[m] + kc*1024;
            char* dst = smc + BBASE + m*BTILE;
#pragma unroll
            for (int i = 0; i < 2; i++) {
                const int q = tid + i*512;
                const int f = q >> 2, seg = q & 3;
                *(uint4*)(dst + f*BSTRIDE + seg*16) = src[q];
            }
        }
        __syncthreads();
#pragma unroll
        for (int kk = 0; kk < 2; kk++) {
            const uint32_t ak = aoff + (uint32_t)(kc*64 + kk*32);
            uint32_t aXh[4], aXl[4], aHh[4], aHl[4], aVh[4], aVl[4];
            ldsm4(ak,             aXh[0], aXh[1], aXh[2], aXh[3]);
            ldsm4(ak + ATILE,     aXl[0], aXl[1], aXl[2], aXl[3]);
            ldsm4(ak + 2*ATILE,   aHh[0], aHh[1], aHh[2], aHh[3]);
            ldsm4(ak + 3*ATILE,   aHl[0], aHl[1], aHl[2], aHl[3]);
            ldsm4(ak + 4*ATILE,   aVh[0], aVh[1], aVh[2], aVh[3]);
            ldsm4(ak + 5*ATILE,   aVl[0], aVl[1], aVl[2], aVl[3]);
            uint32_t b[4][2][4];
            const uint32_t bk = boff + (uint32_t)(kk*32);
#pragma unroll
            for (int m = 0; m < 4; m++)
#pragma unroll
                for (int p = 0; p < 2; p++)
                    ldsm4(bk + m*BTILE + p*16*BSTRIDE,
                          b[m][p][0], b[m][p][1], b[m][p][2], b[m][p][3]);
#pragma unroll
            for (int nt = 0; nt < 4; nt++) {
                const int p = nt >> 1, s2 = nt & 1;
                const uint32_t meh0 = b[0][p][s2], meh1 = b[0][p][s2+2];
                const uint32_t mel0 = b[1][p][s2], mel1 = b[1][p][s2+2];
                const uint32_t ceh0 = b[2][p][s2], ceh1 = b[2][p][s2+2];
                const uint32_t cel0 = b[3][p][s2], cel1 = b[3][p][s2+2];
                mma_bf16(cm[nt], aXh, meh0, meh1);
                mma_bf16(cm[nt], aXh, mel0, mel1);
                mma_bf16(cm[nt], aXl, meh0, meh1);
                mma_bf16(cm[nt], aHh, ceh0, ceh1);
                mma_bf16(cm[nt], aHh, cel0, cel1);
                mma_bf16(cm[nt], aHl, ceh0, ceh1);
                mma_bf16(cs[nt], aVh, meh0, meh1);
                mma_bf16(cs[nt], aVh, mel0, mel1);
                mma_bf16(cs[nt], aVl, meh0, meh1);
            }
        }
    }

    // ---- epilogue ----
    const int r1 = lane >> 2, c2o = (lane & 3)*2;
    const int grow = tok0 + row0 + r1;
#pragma unroll
    for (int nt = 0; nt < 4; nt++) {
        const int col = col0 + nt*8 + c2o;
        const size_t o0 = (size_t)grow*256 + col;
        const size_t o1 = (size_t)(grow + 8)*256 + col;
        *(float2*)(out_means + o0) = make_float2(cm[nt][0], cm[nt][1]);
        *(float2*)(out_means + o1) = make_float2(cm[nt][2], cm[nt][3]);
        *(float2*)(out_stds  + o0) = make_float2(cs[nt][0], cs[nt][1]);
        *(float2*)(out_stds  + o1) = make_float2(cs[nt][2], cs[nt][3]);
    }
}

// ---------------- launch ----------------
extern "C" void kernel_launch(void* const* d_in, const int* in_sizes, int n_in,
                              void* d_out, int out_size) {
    const float* Z   = (const float*)d_in[0];
    const float* obs = (const float*)d_in[1];
    const float* D   = (const float*)d_in[2];
    const float* cW  = (const float*)d_in[3];
    const float* cb  = (const float*)d_in[4];
    const float* E_w = (const float*)d_in[5];
    const float* B_w = (const float*)d_in[6];
    const float* C_w = (const float*)d_in[7];
    const float* M_w = (const float*)d_in[8];
    const float* imp = (const float*)d_in[9];
    const float* ilv = (const float*)d_in[10];
    const float* ylv = (const float*)d_in[11];

    float* out        = (float*)d_out;
    float* out_means  = out;
    float* out_stds   = out + (size_t)BTn * LDn;
    float* out_alphas = out + 2 * (size_t)BTn * LDn;

    cudaFuncSetAttribute(k_token, cudaFuncAttributeMaxDynamicSharedMemorySize, SMEM_TOKEN);
    cudaFuncSetAttribute(k_fused, cudaFuncAttributeMaxDynamicSharedMemorySize, SMEM_OUT);

    k_pre_vec<<<64, 256>>>(E_w, D, imp, ilv, ylv);
    k_pre_transpose<<<dim3(8,8), dim3(32,32)>>>(B_w);
    k_pre_gemm<<<dim3(8,8,2), dim3(32,32)>>>(E_w, M_w, C_w);
    k_pre_wbc<<<1024, 256>>>(B_w, cW);
    k_token<<<BTn/32, 512, SMEM_TOKEN>>>(Z, obs, cb, out_alphas);
    k_scan2<<<Bn, 512>>>();
    k_fused<<<BTn/32, 512, SMEM_OUT>>>(Z, out_alphas, out_means, out_stds);
}

// round 9
// speedup vs baseline: 1.4969x; 1.1429x over previous
#include <cuda_runtime.h>
#include <cuda_bf16.h>
#include <math.h>
#include <stdint.h>

#define EPSF 1e-6f
#define Bn 16
#define Tn 2048
#define LDn 256
#define NBn 32
#define BTn (Bn*Tn)
#define NCHUNK 64

typedef unsigned long long ull;

// ---------- warp-mma helpers ----------
static __device__ __forceinline__ uint32_t smem_u32(const void* p) {
    uint32_t a;
    asm("{ .reg .u64 t; cvta.to.shared.u64 t, %1; cvt.u32.u64 %0, t; }" : "=r"(a) : "l"(p));
    return a;
}
__device__ __forceinline__ void ldsm4(uint32_t addr, uint32_t& r0, uint32_t& r1,
                                      uint32_t& r2, uint32_t& r3) {
    asm volatile("ldmatrix.sync.aligned.m8n8.x4.shared.b16 {%0,%1,%2,%3}, [%4];"
                 : "=r"(r0), "=r"(r1), "=r"(r2), "=r"(r3) : "r"(addr));
}
__device__ __forceinline__ void mma_bf16(float* c, const uint32_t* a, uint32_t b0, uint32_t b1) {
    asm volatile(
        "mma.sync.aligned.m16n8k16.row.col.f32.bf16.bf16.f32 "
        "{%0,%1,%2,%3},{%4,%5,%6,%7},{%8,%9},{%0,%1,%2,%3};"
        : "+f"(c[0]), "+f"(c[1]), "+f"(c[2]), "+f"(c[3])
        : "r"(a[0]), "r"(a[1]), "r"(a[2]), "r"(a[3]), "r"(b0), "r"(b1));
}

// -------- scratch (device globals) --------
__device__ float g_eA[(size_t)BTn*LDn];
__device__ float g_inv[(size_t)BTn*LDn];
__device__ float g_aggA[Bn*NCHUNK*512];
__device__ float g_aggB[Bn*NCHUNK*512];
__device__ float g_carry[Bn*NCHUNK*512];
__device__ float g_Abasis[NBn*LDn];
__device__ float g_initmv[512];
__device__ float g_yvar[LDn];
// bf16 split weights, layout [kchunk(8)][row(256)][k(32)] per matrix
__device__ __align__(16) __nv_bfloat16 g_WMEh[65536];
__device__ __align__(16) __nv_bfloat16 g_WMEl[65536];
__device__ __align__(16) __nv_bfloat16 g_WCEh[65536];
__device__ __align__(16) __nv_bfloat16 g_WCEl[65536];
__device__ __align__(16) __nv_bfloat16 g_Bwh[65536];
__device__ __align__(16) __nv_bfloat16 g_Bwl[65536];

// ---------------- precompute: vectors (warp-per-output) + A_basis ----------------
__global__ void k_pre_vec(const float* __restrict__ E_w, const float* __restrict__ D,
                          const float* __restrict__ imp, const float* __restrict__ ilv,
                          const float* __restrict__ ylv) {
    const int tid = threadIdx.x, lane = tid & 31;
    const int w = blockIdx.x*8 + (tid >> 5);
    float s = 0.f;
    if (w < 256) {
#pragma unroll
        for (int j = 0; j < 8; j++) { int k = lane + 32*j; s = fmaf(E_w[k*256 + w], imp[k], s); }
    } else {
        const int i = w - 256;
#pragma unroll
        for (int j = 0; j < 8; j++) {
            int k = lane + 32*j; float e = E_w[k*256 + i];
            s = fmaf(e*e, expf(ilv[k]) + EPSF, s);
        }
    }
#pragma unroll
    for (int off = 16; off > 0; off >>= 1) s += __shfl_xor_sync(0xffffffffu, s, off);
    if (lane == 0) {
        g_initmv[w] = s;
        if (w < 256) g_yvar[w] = expf(ylv[w]) + EPSF;
    }
    const int gid = blockIdx.x*256 + tid;
    if (gid < NBn*LDn) g_Abasis[gid] = -(expf(D[gid]) + EPSF);
}

// ---------------- precompute: B_w bf16 split, [kc][e][kk] ----------------
__global__ void k_pre_bw(const float* __restrict__ B_w) {
    const int e = blockIdx.x, d = threadIdx.x;
    const float v = B_w[e*256 + d];
    __nv_bfloat16 h = __float2bfloat16(v);
    __nv_bfloat16 l = __float2bfloat16(v - __bfloat162float(h));
    const int idx = (d >> 5)*8192 + e*32 + (d & 31);
    g_Bwh[idx] = h;
    g_Bwl[idx] = l;
}

// ---------------- precompute: W_ME/W_CE bf16 splits, [kc][f][kk] ----------------
__global__ void k_pre_gemm(const float* __restrict__ E_w, const float* __restrict__ M_w,
                           const float* __restrict__ C_w) {
    const float* X = (blockIdx.z == 0) ? M_w : C_w;
    __nv_bfloat16* oh = (blockIdx.z == 0) ? g_WMEh : g_WCEh;
    __nv_bfloat16* ol = (blockIdx.z == 0) ? g_WMEl : g_WCEl;
    __shared__ float sE[32][33];
    __shared__ float sX[32][33];
    const int tx = threadIdx.x, ty = threadIdx.y;
    const int d0 = blockIdx.x*32, f0 = blockIdx.y*32;
    float acc = 0.f;
    for (int e0 = 0; e0 < 256; e0 += 32) {
        sE[ty][tx] = E_w[(e0+ty)*256 + d0 + tx];
        sX[ty][tx] = X[(f0+ty)*256 + e0 + tx];
        __syncthreads();
#pragma unroll
        for (int e = 0; e < 32; e++) acc = fmaf(sE[e][ty], sX[tx][e], acc);
        __syncthreads();
    }
    const int f = f0 + tx, d = d0 + ty;
    __nv_bfloat16 h = __float2bfloat16(acc);
    __nv_bfloat16 l = __float2bfloat16(acc - __bfloat162float(h));
    const int idx = (d >> 5)*8192 + f*32 + (d & 31);
    oh[idx] = h;
    ol[idx] = l;
}

// ---------------- shared tile geometry ----------------
#define ASTRIDE 528
#define ATILE   16896
#define BSTRIDE 80
#define BTILE   20480

__device__ __forceinline__ void put_split(char* hB, char* lB, int r, int d, float v) {
    __nv_bfloat16 h = __float2bfloat16(v);
    __nv_bfloat16 l = __float2bfloat16(v - __bfloat162float(h));
    const uint32_t off = (uint32_t)r*ASTRIDE + (uint32_t)d*2;
    *(__nv_bfloat16*)(hB + off) = h;
    *(__nv_bfloat16*)(lB + off) = l;
}

// ---------------- k_token: mma alphas + logits + softmax + exp + aggregates ----------------
// A area [0, 33792): Z hi/lo tiles; later sCW (32x257 f32) then sPar (8x256 f32)
// B area [33792, 74752): B staging hi/lo; later sAL (32x256 f32)
// sCoef at 74752 (32x33 f32), sT at 78976 (32 f32)
#define TBBASE   33792
#define TCOEF    74752
#define TTIME    78976
#define SMEM_TOKEN (TTIME + 128)
__global__ void __launch_bounds__(512, 2) k_token(const float* __restrict__ Z,
        const float* __restrict__ obs, const float* __restrict__ cW,
        const float* __restrict__ cb, float* __restrict__ alphas_out) {
    extern __shared__ char smc[];
    const uint32_t sbase = smem_u32(smc);
    float* sCoef = (float*)(smc + TCOEF);
    float* sT    = (float*)(smc + TTIME);
    const int tid = threadIdx.x;
    const int bc = blockIdx.x;
    const int tok0 = bc * 32;

    // ---- phase 1: Z -> bf16 split tiles ----
    {
        const int d = tid & 255;
        const int rb0 = (tid >> 8) * 16;
#pragma unroll 4
        for (int r = rb0; r < rb0 + 16; r++)
            put_split(smc, smc + ATILE, r, d, Z[(size_t)(tok0 + r)*256 + d]);
        if (tid < 32) sT[tid] = obs[tok0 + tid];
    }

    // ---- phase 2: alphas = Z @ B_w^T via 3-term split mma ----
    const int lane = tid & 31, wid = tid >> 5;
    const int row0 = (wid & 1) * 16;
    const int col0 = (wid >> 1) * 32;
    float cm[4][4];
#pragma unroll
    for (int nt = 0; nt < 4; nt++)
#pragma unroll
        for (int q = 0; q < 4; q++) cm[nt][q] = 0.f;

    const uint32_t aoff = sbase + (uint32_t)(row0 + (lane & 15))*ASTRIDE + (uint32_t)(lane >> 4)*16;
    const uint32_t boff = sbase + TBBASE + (uint32_t)(col0 + (lane & 15))*BSTRIDE + (uint32_t)(lane >> 4)*16;

    for (int kc = 0; kc < 8; kc++) {
        __syncthreads();
#pragma unroll
        for (int m = 0; m < 2; m++) {
            const uint4* src = ((m == 0) ? (const uint4*)g_Bwh : (const uint4*)g_Bwl) + kc*1024;
            char* dst = smc + TBBASE + m*BTILE;
#pragma unroll
            for (int i = 0; i < 2; i++) {
                const int q = tid + i*512;
                const int f = q >> 2, seg = q & 3;
                *(uint4*)(dst + f*BSTRIDE + seg*16) = src[q];
            }
        }
        __syncthreads();
#pragma unroll
        for (int kk = 0; kk < 2; kk++) {
            const uint32_t ak = aoff + (uint32_t)(kc*64 + kk*32);
            uint32_t aZh[4], aZl[4];
            ldsm4(ak,         aZh[0], aZh[1], aZh[2], aZh[3]);
            ldsm4(ak + ATILE, aZl[0], aZl[1], aZl[2], aZl[3]);
            uint32_t b[2][2][4];
            const uint32_t bk = boff + (uint32_t)(kk*32);
#pragma unroll
            for (int m = 0; m < 2; m++)
#pragma unroll
                for (int p = 0; p < 2; p++)
                    ldsm4(bk + m*BTILE + p*16*BSTRIDE,
                          b[m][p][0], b[m][p][1], b[m][p][2], b[m][p][3]);
#pragma unroll
            for (int nt = 0; nt < 4; nt++) {
                const int p = nt >> 1, s2 = nt & 1;
                const uint32_t bh0 = b[0][p][s2], bh1 = b[0][p][s2+2];
                const uint32_t bl0 = b[1][p][s2], bl1 = b[1][p][s2+2];
                mma_bf16(cm[nt], aZh, bh0, bh1);
                mma_bf16(cm[nt], aZh, bl0, bl1);
                mma_bf16(cm[nt], aZl, bh0, bh1);
            }
        }
    }
    __syncthreads();   // A + B tiles dead; safe to alias

    // ---- epilogue: alphas -> sAL (B area) + gmem; cW -> sCW (A area) ----
    float* sAL = (float*)(smc + TBBASE);
    float* sCW = (float*)smc;
    {
        const int r1 = lane >> 2, c2o = (lane & 3)*2;
#pragma unroll
        for (int nt = 0; nt < 4; nt++) {
            const int col = col0 + nt*8 + c2o;
            const int lr0 = row0 + r1, lr1 = row0 + r1 + 8;
            sAL[lr0*256 + col]     = cm[nt][0];
            sAL[lr0*256 + col + 1] = cm[nt][1];
            sAL[lr1*256 + col]     = cm[nt][2];
            sAL[lr1*256 + col + 1] = cm[nt][3];
            *(float2*)(alphas_out + (size_t)(tok0+lr0)*256 + col) = make_float2(cm[nt][0], cm[nt][1]);
            *(float2*)(alphas_out + (size_t)(tok0+lr1)*256 + col) = make_float2(cm[nt][2], cm[nt][3]);
        }
        for (int idx = tid; idx < 32*256; idx += 512)
            sCW[(idx >> 8)*257 + (idx & 255)] = cW[idx];
    }
    __syncthreads();

    // ---- phase 3: logits + softmax (warp = 2 tokens, lane = basis) ----
#pragma unroll
    for (int rr = 0; rr < 2; rr++) {
        const int r = wid*2 + rr;
        const float4* arow = (const float4*)(sAL + r*256);
        const float* crow = sCW + lane*257;
        float lg = cb[lane];
#pragma unroll 8
        for (int q = 0; q < 64; q++) {
            float4 a4 = arow[q];
            lg = fmaf(a4.x, crow[4*q+0], lg);
            lg = fmaf(a4.y, crow[4*q+1], lg);
            lg = fmaf(a4.z, crow[4*q+2], lg);
            lg = fmaf(a4.w, crow[4*q+3], lg);
        }
        float m = lg;
#pragma unroll
        for (int off = 16; off > 0; off >>= 1)
            m = fmaxf(m, __shfl_xor_sync(0xffffffffu, m, off));
        const float e = __expf(lg - m);
        float s = e;
#pragma unroll
        for (int off = 16; off > 0; off >>= 1)
            s += __shfl_xor_sync(0xffffffffu, s, off);
        sCoef[r*33 + lane] = e / s;
    }
    __syncthreads();

    // ---- phase 4: A_mat + exp terms + half-chunk aggregates ----
    const int c = tid & 255;
    const int h = tid >> 8;
    const int rbase = h * 16;
    float am[16];
#pragma unroll
    for (int rr = 0; rr < 16; rr++) am[rr] = 0.f;
#pragma unroll 4
    for (int n = 0; n < 32; n++) {
        const float ab = g_Abasis[n*256 + c];
#pragma unroll
        for (int rr = 0; rr < 16; rr++)
            am[rr] = fmaf(sCoef[(rbase+rr)*33 + n], ab, am[rr]);
    }
    float aAm = 1.f, bBm = 0.f, aAv = 1.f, bBv = 0.f;
#pragma unroll 4
    for (int rr = 0; rr < 16; rr++) {
        const int r = rbase + rr;
        const float a = am[rr];
        const float t = sT[r];
        const float eAm = __expf(a * t);
        const float inv = __fdividef(1.0f, a);
        const float al  = sAL[r*256 + c];
        const float eBm = (eAm - 1.f) * inv * al;
        const float eAv = eAm * eAm;
        const float eBv = 0.5f*(eAv - 1.f)*inv + EPSF;
        const size_t o = (size_t)(tok0 + r)*256 + c;
        g_eA[o]  = eAm;
        g_inv[o] = inv;
        bBm = fmaf(eAm, bBm, eBm); aAm *= eAm;
        bBv = fmaf(eAv, bBv, eBv); aAv *= eAv;
    }
    float* sPar = (float*)smc;   // A area (sCW dead)
    sPar[(h*4+0)*256 + c] = aAm;
    sPar[(h*4+1)*256 + c] = bBm;
    sPar[(h*4+2)*256 + c] = aAv;
    sPar[(h*4+3)*256 + c] = bBv;
    __syncthreads();
    if (tid < 256) {
        const float A0m = sPar[tid],        B0m = sPar[256 + tid];
        const float A0v = sPar[512 + tid],  B0v = sPar[768 + tid];
        const float A1m = sPar[1024 + tid], B1m = sPar[1280 + tid];
        const float A1v = sPar[1536 + tid], B1v = sPar[1792 + tid];
        g_aggA[bc*512 + tid]       = A1m * A0m;
        g_aggB[bc*512 + tid]       = fmaf(A1m, B0m, B1m);
        g_aggA[bc*512 + 256 + tid] = A1v * A0v;
        g_aggB[bc*512 + 256 + tid] = fmaf(A1v, B0v, B1v);
    }
}

// ---------------- scan over chunk aggregates ----------------
__global__ void k_scan2() {
    const int b = blockIdx.x;
    const int c = threadIdx.x;
    float s = g_initmv[c];
#pragma unroll 4
    for (int j = 0; j < NCHUNK; j++) {
        const int idx = (b*NCHUNK + j)*512 + c;
        g_carry[idx] = s;
        s = fmaf(g_aggA[idx], s, g_aggB[idx]);
    }
}

// ---------------- k_fused: scan-apply + warp-mma output GEMMs (R8 proven) ----------------
#define BBASE   (6*ATILE)
#define SMEM_OUT (BBASE + 4*BTILE)

__global__ void __launch_bounds__(512, 1) k_fused(const float* __restrict__ Z,
        const float* __restrict__ alphas,
        float* __restrict__ out_means, float* __restrict__ out_stds) {
    extern __shared__ char smc[];
    const uint32_t sbase = smem_u32(smc);
    const int tid = threadIdx.x;
    const int bc = blockIdx.x;
    const int tok0 = bc * 32;

    {
        const int d = tid & 255;
        if (tid < 256) {
            float s = g_carry[bc*512 + d];
#pragma unroll 4
            for (int r = 0; r < 32; r++) {
                const size_t o = (size_t)(tok0 + r)*256 + d;
                const float eA = g_eA[o], iv = g_inv[o], al = alphas[o];
                s = fmaf(eA, s, (eA - 1.f)*iv*al);
                put_split(smc, smc + ATILE, r, d, s);
                put_split(smc + 2*ATILE, smc + 3*ATILE, r, d, Z[o]);
            }
        } else {
            float s = g_carry[bc*512 + 256 + d];
            const float yv = g_yvar[d];
#pragma unroll 4
            for (int r = 0; r < 32; r++) {
                const size_t o = (size_t)(tok0 + r)*256 + d;
                const float eA = g_eA[o], iv = g_inv[o];
                const float eAv = eA * eA;
                s = fmaf(eAv, s, 0.5f*(eAv - 1.f)*iv + EPSF);
                put_split(smc + 4*ATILE, smc + 5*ATILE, r, d, sqrtf(s + yv));
            }
        }
    }

    const int lane = tid & 31, wid = tid >> 5;
    const int row0 = (wid & 1) * 16;
    const int col0 = (wid >> 1) * 32;
    float cm[4][4], cs[4][4];
#pragma unroll
    for (int nt = 0; nt < 4; nt++)
#pragma unroll
        for (int q = 0; q < 4; q++) { cm[nt][q] = 0.f; cs[nt][q] = 0.f; }

    const uint32_t aoff = sbase + (uint32_t)(row0 + (lane & 15))*ASTRIDE + (uint32_t)(lane >> 4)*16;
    const uint32_t boff = sbase + BBASE + (uint32_t)(col0 + (lane & 15))*BSTRIDE + (uint32_t)(lane >> 4)*16;
    const uint4* gB[4] = { (const uint4*)g_WMEh, (const uint4*)g_WMEl,
                           (const uint4*)g_WCEh, (const uint4*)g_WCEl };

    for (int kc = 0; kc < 8; kc++) {
        __syncthreads();
#pragma unroll
        for (int m = 0; m < 4; m++) {
            const uint4* src = gB[m] + kc*1024;
            char* dst = smc + BBASE + m*BTILE;
#pragma unroll
            for (int i = 0; i < 2; i++) {
                const int q = tid + i*512;
                const int f = q >> 2, seg = q & 3;
                *(uint4*)(dst + f*BSTRIDE + seg*16) = src[q];
            }
        }
        __syncthreads();
#pragma unroll
        for (int kk = 0; kk < 2; kk++) {
            const uint32_t ak = aoff + (uint32_t)(kc*64 + kk*32);
            uint32_t aXh[4], aXl[4], aHh[4], aHl[4], aVh[4], aVl[4];
            ldsm4(ak,             aXh[0], aXh[1], aXh[2], aXh[3]);
            ldsm4(ak + ATILE,     aXl[0], aXl[1], aXl[2], aXl[3]);
            ldsm4(ak + 2*ATILE,   aHh[0], aHh[1], aHh[2], aHh[3]);
            ldsm4(ak + 3*ATILE,   aHl[0], aHl[1], aHl[2], aHl[3]);
            ldsm4(ak + 4*ATILE,   aVh[0], aVh[1], aVh[2], aVh[3]);
            ldsm4(ak + 5*ATILE,   aVl[0], aVl[1], aVl[2], aVl[3]);
            uint32_t b[4][2][4];
            const uint32_t bk = boff + (uint32_t)(kk*32);
#pragma unroll
            for (int m = 0; m < 4; m++)
#pragma unroll
                for (int p = 0; p < 2; p++)
                    ldsm4(bk + m*BTILE + p*16*BSTRIDE,
                          b[m][p][0], b[m][p][1], b[m][p][2], b[m][p][3]);
#pragma unroll
            for (int nt = 0; nt < 4; nt++) {
                const int p = nt >> 1, s2 = nt & 1;
                const uint32_t meh0 = b[0][p][s2], meh1 = b[0][p][s2+2];
                const uint32_t mel0 = b[1][p][s2], mel1 = b[1][p][s2+2];
                const uint32_t ceh0 = b[2][p][s2], ceh1 = b[2][p][s2+2];
                const uint32_t cel0 = b[3][p][s2], cel1 = b[3][p][s2+2];
                mma_bf16(cm[nt], aXh, meh0, meh1);
                mma_bf16(cm[nt], aXh, mel0, mel1);
                mma_bf16(cm[nt], aXl, meh0, meh1);
                mma_bf16(cm[nt], aHh, ceh0, ceh1);
                mma_bf16(cm[nt], aHh, cel0, cel1);
                mma_bf16(cm[nt], aHl, ceh0, ceh1);
                mma_bf16(cs[nt], aVh, meh0, meh1);
                mma_bf16(cs[nt], aVh, mel0, mel1);
                mma_bf16(cs[nt], aVl, meh0, meh1);
            }
        }
    }

    const int r1 = lane >> 2, c2o = (lane & 3)*2;
    const int grow = tok0 + row0 + r1;
#pragma unroll
    for (int nt = 0; nt < 4; nt++) {
        const int col = col0 + nt*8 + c2o;
        const size_t o0 = (size_t)grow*256 + col;
        const size_t o1 = (size_t)(grow + 8)*256 + col;
        *(float2*)(out_means + o0) = make_float2(cm[nt][0], cm[nt][1]);
        *(float2*)(out_means + o1) = make_float2(cm[nt][2], cm[nt][3]);
        *(float2*)(out_stds  + o0) = make_float2(cs[nt][0], cs[nt][1]);
        *(float2*)(out_stds  + o1) = make_float2(cs[nt][2], cs[nt][3]);
    }
}

// ---------------- launch ----------------
extern "C" void kernel_launch(void* const* d_in, const int* in_sizes, int n_in,
                              void* d_out, int out_size) {
    const float* Z   = (const float*)d_in[0];
    const float* obs = (const float*)d_in[1];
    const float* D   = (const float*)d_in[2];
    const float* cW  = (const float*)d_in[3];
    const float* cb  = (const float*)d_in[4];
    const float* E_w = (const float*)d_in[5];
    const float* B_w = (const float*)d_in[6];
    const float* C_w = (const float*)d_in[7];
    const float* M_w = (const float*)d_in[8];
    const float* imp = (const float*)d_in[9];
    const float* ilv = (const float*)d_in[10];
    const float* ylv = (const float*)d_in[11];

    float* out        = (float*)d_out;
    float* out_means  = out;
    float* out_stds   = out + (size_t)BTn * LDn;
    float* out_alphas = out + 2 * (size_t)BTn * LDn;

    cudaFuncSetAttribute(k_token, cudaFuncAttributeMaxDynamicSharedMemorySize, SMEM_TOKEN);
    cudaFuncSetAttribute(k_fused, cudaFuncAttributeMaxDynamicSharedMemorySize, SMEM_OUT);

    k_pre_vec<<<64, 256>>>(E_w, D, imp, ilv, ylv);
    k_pre_bw<<<256, 256>>>(B_w);
    k_pre_gemm<<<dim3(8,8,2), dim3(32,32)>>>(E_w, M_w, C_w);
    k_token<<<BTn/32, 512, SMEM_TOKEN>>>(Z, obs, cW, cb, out_alphas);
    k_scan2<<<Bn, 512>>>();
    k_fused<<<BTn/32, 512, SMEM_OUT>>>(Z, out_alphas, out_means, out_stds);
}

// round 10
// speedup vs baseline: 1.6139x; 1.0782x over previous
#include <cuda_runtime.h>
#include <cuda_bf16.h>
#include <math.h>
#include <stdint.h>

#define EPSF 1e-6f
#define Bn 16
#define Tn 2048
#define LDn 256
#define NBn 32
#define BTn (Bn*Tn)
#define NCHUNK 64

typedef unsigned long long ull;

// ---------- warp-mma helpers ----------
static __device__ __forceinline__ uint32_t smem_u32(const void* p) {
    uint32_t a;
    asm("{ .reg .u64 t; cvta.to.shared.u64 t, %1; cvt.u32.u64 %0, t; }" : "=r"(a) : "l"(p));
    return a;
}
__device__ __forceinline__ void ldsm4(uint32_t addr, uint32_t& r0, uint32_t& r1,
                                      uint32_t& r2, uint32_t& r3) {
    asm volatile("ldmatrix.sync.aligned.m8n8.x4.shared.b16 {%0,%1,%2,%3}, [%4];"
                 : "=r"(r0), "=r"(r1), "=r"(r2), "=r"(r3) : "r"(addr));
}
__device__ __forceinline__ void mma_bf16(float* c, const uint32_t* a, uint32_t b0, uint32_t b1) {
    asm volatile(
        "mma.sync.aligned.m16n8k16.row.col.f32.bf16.bf16.f32 "
        "{%0,%1,%2,%3},{%4,%5,%6,%7},{%8,%9},{%0,%1,%2,%3};"
        : "+f"(c[0]), "+f"(c[1]), "+f"(c[2]), "+f"(c[3])
        : "r"(a[0]), "r"(a[1]), "r"(a[2]), "r"(a[3]), "r"(b0), "r"(b1));
}

// -------- scratch (device globals) --------
__device__ float2 g_eAiv[(size_t)BTn*LDn];   // (exp(A t), 1/A) packed
__device__ float g_aggA[Bn*NCHUNK*512];
__device__ float g_aggB[Bn*NCHUNK*512];
__device__ float g_carry[Bn*NCHUNK*512];
__device__ float g_Abasis[NBn*LDn];
__device__ float g_initmv[512];
__device__ float g_yvar[LDn];
// bf16 split weights, layout [kchunk(8)][row(256)][k(32)] per matrix
__device__ __align__(16) __nv_bfloat16 g_WMEh[65536];
__device__ __align__(16) __nv_bfloat16 g_WMEl[65536];
__device__ __align__(16) __nv_bfloat16 g_WCEh[65536];
__device__ __align__(16) __nv_bfloat16 g_WCEl[65536];
__device__ __align__(16) __nv_bfloat16 g_Bwh[65536];
__device__ __align__(16) __nv_bfloat16 g_Bwl[65536];

// ---------------- precompute: vectors (warp-per-output) + A_basis ----------------
__global__ void k_pre_vec(const float* __restrict__ E_w, const float* __restrict__ D,
                          const float* __restrict__ imp, const float* __restrict__ ilv,
                          const float* __restrict__ ylv) {
    const int tid = threadIdx.x, lane = tid & 31;
    const int w = blockIdx.x*8 + (tid >> 5);
    float s = 0.f;
    if (w < 256) {
#pragma unroll
        for (int j = 0; j < 8; j++) { int k = lane + 32*j; s = fmaf(E_w[k*256 + w], imp[k], s); }
    } else {
        const int i = w - 256;
#pragma unroll
        for (int j = 0; j < 8; j++) {
            int k = lane + 32*j; float e = E_w[k*256 + i];
            s = fmaf(e*e, expf(ilv[k]) + EPSF, s);
        }
    }
#pragma unroll
    for (int off = 16; off > 0; off >>= 1) s += __shfl_xor_sync(0xffffffffu, s, off);
    if (lane == 0) {
        g_initmv[w] = s;
        if (w < 256) g_yvar[w] = expf(ylv[w]) + EPSF;
    }
    const int gid = blockIdx.x*256 + tid;
    if (gid < NBn*LDn) g_Abasis[gid] = -(expf(D[gid]) + EPSF);
}

// ---------------- precompute: B_w bf16 split, [kc][e][kk] ----------------
__global__ void k_pre_bw(const float* __restrict__ B_w) {
    const int e = blockIdx.x, d = threadIdx.x;
    const float v = B_w[e*256 + d];
    __nv_bfloat16 h = __float2bfloat16(v);
    __nv_bfloat16 l = __float2bfloat16(v - __bfloat162float(h));
    const int idx = (d >> 5)*8192 + e*32 + (d & 31);
    g_Bwh[idx] = h;
    g_Bwl[idx] = l;
}

// ---------------- precompute: W_ME/W_CE bf16 splits, [kc][f][kk] ----------------
__global__ void k_pre_gemm(const float* __restrict__ E_w, const float* __restrict__ M_w,
                           const float* __restrict__ C_w) {
    const float* X = (blockIdx.z == 0) ? M_w : C_w;
    __nv_bfloat16* oh = (blockIdx.z == 0) ? g_WMEh : g_WCEh;
    __nv_bfloat16* ol = (blockIdx.z == 0) ? g_WMEl : g_WCEl;
    __shared__ float sE[32][33];
    __shared__ float sX[32][33];
    const int tx = threadIdx.x, ty = threadIdx.y;
    const int d0 = blockIdx.x*32, f0 = blockIdx.y*32;
    float acc = 0.f;
    for (int e0 = 0; e0 < 256; e0 += 32) {
        sE[ty][tx] = E_w[(e0+ty)*256 + d0 + tx];
        sX[ty][tx] = X[(f0+ty)*256 + e0 + tx];
        __syncthreads();
#pragma unroll
        for (int e = 0; e < 32; e++) acc = fmaf(sE[e][ty], sX[tx][e], acc);
        __syncthreads();
    }
    const int f = f0 + tx, d = d0 + ty;
    __nv_bfloat16 h = __float2bfloat16(acc);
    __nv_bfloat16 l = __float2bfloat16(acc - __bfloat162float(h));
    const int idx = (d >> 5)*8192 + f*32 + (d & 31);
    oh[idx] = h;
    ol[idx] = l;
}

// ---------------- shared tile geometry ----------------
#define ASTRIDE 528
#define ATILE   16896
#define BSTRIDE 80
#define BTILE   20480

__device__ __forceinline__ void put_split(char* hB, char* lB, int r, int d, float v) {
    __nv_bfloat16 h = __float2bfloat16(v);
    __nv_bfloat16 l = __float2bfloat16(v - __bfloat162float(h));
    const uint32_t off = (uint32_t)r*ASTRIDE + (uint32_t)d*2;
    *(__nv_bfloat16*)(hB + off) = h;
    *(__nv_bfloat16*)(lB + off) = l;
}

// ---------------- k_token: mma alphas + logits + softmax + exp + aggregates ----------------
#define TBBASE   33792
#define TCOEF    74752
#define TTIME    78976
#define SMEM_TOKEN (TTIME + 128)
__global__ void __launch_bounds__(512, 2) k_token(const float* __restrict__ Z,
        const float* __restrict__ obs, const float* __restrict__ cW,
        const float* __restrict__ cb, float* __restrict__ alphas_out) {
    extern __shared__ char smc[];
    const uint32_t sbase = smem_u32(smc);
    float* sCoef = (float*)(smc + TCOEF);
    float* sT    = (float*)(smc + TTIME);
    const int tid = threadIdx.x;
    const int bc = blockIdx.x;
    const int tok0 = bc * 32;

    // ---- phase 1: Z -> bf16 split tiles ----
    {
        const int d = tid & 255;
        const int rb0 = (tid >> 8) * 16;
#pragma unroll 4
        for (int r = rb0; r < rb0 + 16; r++)
            put_split(smc, smc + ATILE, r, d, Z[(size_t)(tok0 + r)*256 + d]);
        if (tid < 32) sT[tid] = obs[tok0 + tid];
    }

    // ---- phase 2: alphas = Z @ B_w^T via 3-term split mma ----
    const int lane = tid & 31, wid = tid >> 5;
    const int row0 = (wid & 1) * 16;
    const int col0 = (wid >> 1) * 32;
    float cm[4][4];
#pragma unroll
    for (int nt = 0; nt < 4; nt++)
#pragma unroll
        for (int q = 0; q < 4; q++) cm[nt][q] = 0.f;

    const uint32_t aoff = sbase + (uint32_t)(row0 + (lane & 15))*ASTRIDE + (uint32_t)(lane >> 4)*16;
    const uint32_t boff = sbase + TBBASE + (uint32_t)(col0 + (lane & 15))*BSTRIDE + (uint32_t)(lane >> 4)*16;

    for (int kc = 0; kc < 8; kc++) {
        __syncthreads();
#pragma unroll
        for (int m = 0; m < 2; m++) {
            const uint4* src = ((m == 0) ? (const uint4*)g_Bwh : (const uint4*)g_Bwl) + kc*1024;
            char* dst = smc + TBBASE + m*BTILE;
#pragma unroll
            for (int i = 0; i < 2; i++) {
                const int q = tid + i*512;
                const int f = q >> 2, seg = q & 3;
                *(uint4*)(dst + f*BSTRIDE + seg*16) = src[q];
            }
        }
        __syncthreads();
#pragma unroll
        for (int kk = 0; kk < 2; kk++) {
            const uint32_t ak = aoff + (uint32_t)(kc*64 + kk*32);
            uint32_t aZh[4], aZl[4];
            ldsm4(ak,         aZh[0], aZh[1], aZh[2], aZh[3]);
            ldsm4(ak + ATILE, aZl[0], aZl[1], aZl[2], aZl[3]);
            uint32_t b[2][2][4];
            const uint32_t bk = boff + (uint32_t)(kk*32);
#pragma unroll
            for (int m = 0; m < 2; m++)
#pragma unroll
                for (int p = 0; p < 2; p++)
                    ldsm4(bk + m*BTILE + p*16*BSTRIDE,
                          b[m][p][0], b[m][p][1], b[m][p][2], b[m][p][3]);
#pragma unroll
            for (int nt = 0; nt < 4; nt++) {
                const int p = nt >> 1, s2 = nt & 1;
                const uint32_t bh0 = b[0][p][s2], bh1 = b[0][p][s2+2];
                const uint32_t bl0 = b[1][p][s2], bl1 = b[1][p][s2+2];
                mma_bf16(cm[nt], aZh, bh0, bh1);
                mma_bf16(cm[nt], aZh, bl0, bl1);
                mma_bf16(cm[nt], aZl, bh0, bh1);
            }
        }
    }
    __syncthreads();

    // ---- epilogue: alphas -> sAL (B area) + gmem; cW -> sCW (A area) ----
    float* sAL = (float*)(smc + TBBASE);
    float* sCW = (float*)smc;
    {
        const int r1 = lane >> 2, c2o = (lane & 3)*2;
#pragma unroll
        for (int nt = 0; nt < 4; nt++) {
            const int col = col0 + nt*8 + c2o;
            const int lr0 = row0 + r1, lr1 = row0 + r1 + 8;
            sAL[lr0*256 + col]     = cm[nt][0];
            sAL[lr0*256 + col + 1] = cm[nt][1];
            sAL[lr1*256 + col]     = cm[nt][2];
            sAL[lr1*256 + col + 1] = cm[nt][3];
            *(float2*)(alphas_out + (size_t)(tok0+lr0)*256 + col) = make_float2(cm[nt][0], cm[nt][1]);
            *(float2*)(alphas_out + (size_t)(tok0+lr1)*256 + col) = make_float2(cm[nt][2], cm[nt][3]);
        }
        for (int idx = tid; idx < 32*256; idx += 512)
            sCW[(idx >> 8)*257 + (idx & 255)] = cW[idx];
    }
    __syncthreads();

    // ---- phase 3: logits + softmax ----
#pragma unroll
    for (int rr = 0; rr < 2; rr++) {
        const int r = wid*2 + rr;
        const float4* arow = (const float4*)(sAL + r*256);
        const float* crow = sCW + lane*257;
        float lg = cb[lane];
#pragma unroll 8
        for (int q = 0; q < 64; q++) {
            float4 a4 = arow[q];
            lg = fmaf(a4.x, crow[4*q+0], lg);
            lg = fmaf(a4.y, crow[4*q+1], lg);
            lg = fmaf(a4.z, crow[4*q+2], lg);
            lg = fmaf(a4.w, crow[4*q+3], lg);
        }
        float m = lg;
#pragma unroll
        for (int off = 16; off > 0; off >>= 1)
            m = fmaxf(m, __shfl_xor_sync(0xffffffffu, m, off));
        const float e = __expf(lg - m);
        float s = e;
#pragma unroll
        for (int off = 16; off > 0; off >>= 1)
            s += __shfl_xor_sync(0xffffffffu, s, off);
        sCoef[r*33 + lane] = e / s;
    }
    __syncthreads();

    // ---- phase 4: A_mat + exp terms + half-chunk aggregates ----
    const int c = tid & 255;
    const int h = tid >> 8;
    const int rbase = h * 16;
    float am[16];
#pragma unroll
    for (int rr = 0; rr < 16; rr++) am[rr] = 0.f;
#pragma unroll 4
    for (int n = 0; n < 32; n++) {
        const float ab = g_Abasis[n*256 + c];
#pragma unroll
        for (int rr = 0; rr < 16; rr++)
            am[rr] = fmaf(sCoef[(rbase+rr)*33 + n], ab, am[rr]);
    }
    float aAm = 1.f, bBm = 0.f, aAv = 1.f, bBv = 0.f;
#pragma unroll 4
    for (int rr = 0; rr < 16; rr++) {
        const int r = rbase + rr;
        const float a = am[rr];
        const float t = sT[r];
        const float eAm = __expf(a * t);
        const float inv = __fdividef(1.0f, a);
        const float al  = sAL[r*256 + c];
        const float eBm = (eAm - 1.f) * inv * al;
        const float eAv = eAm * eAm;
        const float eBv = 0.5f*(eAv - 1.f)*inv + EPSF;
        const size_t o = (size_t)(tok0 + r)*256 + c;
        g_eAiv[o] = make_float2(eAm, inv);
        bBm = fmaf(eAm, bBm, eBm); aAm *= eAm;
        bBv = fmaf(eAv, bBv, eBv); aAv *= eAv;
    }
    float* sPar = (float*)smc;
    sPar[(h*4+0)*256 + c] = aAm;
    sPar[(h*4+1)*256 + c] = bBm;
    sPar[(h*4+2)*256 + c] = aAv;
    sPar[(h*4+3)*256 + c] = bBv;
    __syncthreads();
    if (tid < 256) {
        const float A0m = sPar[tid],        B0m = sPar[256 + tid];
        const float A0v = sPar[512 + tid],  B0v = sPar[768 + tid];
        const float A1m = sPar[1024 + tid], B1m = sPar[1280 + tid];
        const float A1v = sPar[1536 + tid], B1v = sPar[1792 + tid];
        g_aggA[bc*512 + tid]       = A1m * A0m;
        g_aggB[bc*512 + tid]       = fmaf(A1m, B0m, B1m);
        g_aggA[bc*512 + 256 + tid] = A1v * A0v;
        g_aggB[bc*512 + 256 + tid] = fmaf(A1v, B0v, B1v);
    }
}

// ---------------- scan over chunk aggregates ----------------
__global__ void k_scan2() {
    const int b = blockIdx.x;
    const int c = threadIdx.x;
    float s = g_initmv[c];
#pragma unroll 4
    for (int j = 0; j < NCHUNK; j++) {
        const int idx = (b*NCHUNK + j)*512 + c;
        g_carry[idx] = s;
        s = fmaf(g_aggA[idx], s, g_aggB[idx]);
    }
}

// ---------------- k_fused: two-pass scan-apply + warp-mma output GEMMs ----------------
// Pass A (WME): X tiles (0,1) + V tiles (2,3).  Pass B (WCE): H tiles alias (0,1).
// smem = 4*ATILE + 2*BTILE = 108544 B -> 2 CTAs/SM.
#define FBBASE   (4*ATILE)
#define SMEM_OUT (FBBASE + 2*BTILE)

__global__ void __launch_bounds__(512, 2) k_fused(const float* __restrict__ Z,
        const float* __restrict__ alphas,
        float* __restrict__ out_means, float* __restrict__ out_stds) {
    extern __shared__ char smc[];
    const uint32_t sbase = smem_u32(smc);
    const int tid = threadIdx.x;
    const int bc = blockIdx.x;
    const int tok0 = bc * 32;

    // ---- phase 1a: scan apply -> X (mean) and V (std) split tiles ----
    {
        const int d = tid & 255;
        if (tid < 256) {
            float s = g_carry[bc*512 + d];
#pragma unroll 4
            for (int r = 0; r < 32; r++) {
                const size_t o = (size_t)(tok0 + r)*256 + d;
                const float2 ei = g_eAiv[o];
                const float al = alphas[o];
                s = fmaf(ei.x, s, (ei.x - 1.f)*ei.y*al);
                put_split(smc, smc + ATILE, r, d, s);
            }
        } else {
            float s = g_carry[bc*512 + 256 + d];
            const float yv = g_yvar[d];
#pragma unroll 4
            for (int r = 0; r < 32; r++) {
                const size_t o = (size_t)(tok0 + r)*256 + d;
                const float2 ei = g_eAiv[o];
                const float eAv = ei.x * ei.x;
                s = fmaf(eAv, s, 0.5f*(eAv - 1.f)*ei.y + EPSF);
                put_split(smc + 2*ATILE, smc + 3*ATILE, r, d, sqrtf(s + yv));
            }
        }
    }

    const int lane = tid & 31, wid = tid >> 5;
    const int row0 = (wid & 1) * 16;
    const int col0 = (wid >> 1) * 32;
    float cm[4][4], cs[4][4];
#pragma unroll
    for (int nt = 0; nt < 4; nt++)
#pragma unroll
        for (int q = 0; q < 4; q++) { cm[nt][q] = 0.f; cs[nt][q] = 0.f; }

    const uint32_t aoff = sbase + (uint32_t)(row0 + (lane & 15))*ASTRIDE + (uint32_t)(lane >> 4)*16;
    const uint32_t boff = sbase + FBBASE + (uint32_t)(col0 + (lane & 15))*BSTRIDE + (uint32_t)(lane >> 4)*16;

    // ---- pass A: WME against X (means) and V (stds) ----
    for (int kc = 0; kc < 8; kc++) {
        __syncthreads();
#pragma unroll
        for (int m = 0; m < 2; m++) {
            const uint4* src = ((m == 0) ? (const uint4*)g_WMEh : (const uint4*)g_WMEl) + kc*1024;
            char* dst = smc + FBBASE + m*BTILE;
#pragma unroll
            for (int i = 0; i < 2; i++) {
                const int q = tid + i*512;
                const int f = q >> 2, seg = q & 3;
                *(uint4*)(dst + f*BSTRIDE + seg*16) = src[q];
            }
        }
        __syncthreads();
#pragma unroll
        for (int kk = 0; kk < 2; kk++) {
            const uint32_t ak = aoff + (uint32_t)(kc*64 + kk*32);
            uint32_t aXh[4], aXl[4], aVh[4], aVl[4];
            ldsm4(ak,           aXh[0], aXh[1], aXh[2], aXh[3]);
            ldsm4(ak + ATILE,   aXl[0], aXl[1], aXl[2], aXl[3]);
            ldsm4(ak + 2*ATILE, aVh[0], aVh[1], aVh[2], aVh[3]);
            ldsm4(ak + 3*ATILE, aVl[0], aVl[1], aVl[2], aVl[3]);
            uint32_t b[2][2][4];
            const uint32_t bk = boff + (uint32_t)(kk*32);
#pragma unroll
            for (int m = 0; m < 2; m++)
#pragma unroll
                for (int p = 0; p < 2; p++)
                    ldsm4(bk + m*BTILE + p*16*BSTRIDE,
                          b[m][p][0], b[m][p][1], b[m][p][2], b[m][p][3]);
#pragma unroll
            for (int nt = 0; nt < 4; nt++) {
                const int p = nt >> 1, s2 = nt & 1;
                const uint32_t bh0 = b[0][p][s2], bh1 = b[0][p][s2+2];
                const uint32_t bl0 = b[1][p][s2], bl1 = b[1][p][s2+2];
                mma_bf16(cm[nt], aXh, bh0, bh1);
                mma_bf16(cm[nt], aXh, bl0, bl1);
                mma_bf16(cm[nt], aXl, bh0, bh1);
                mma_bf16(cs[nt], aVh, bh0, bh1);
                mma_bf16(cs[nt], aVh, bl0, bl1);
                mma_bf16(cs[nt], aVl, bh0, bh1);
            }
        }
    }
    __syncthreads();   // pass A mma done; X tiles safe to overwrite

    // ---- phase 1b: H = Z -> tiles 0,1 (aliasing X) ----
    {
        const int d = tid & 255;
        const int rb0 = (tid >> 8) * 16;
#pragma unroll 4
        for (int r = rb0; r < rb0 + 16; r++)
            put_split(smc, smc + ATILE, r, d, Z[(size_t)(tok0 + r)*256 + d]);
    }

    // ---- pass B: WCE against H (means accumulate) ----
    for (int kc = 0; kc < 8; kc++) {
        __syncthreads();
#pragma unroll
        for (int m = 0; m < 2; m++) {
            const uint4* src = ((m == 0) ? (const uint4*)g_WCEh : (const uint4*)g_WCEl) + kc*1024;
            char* dst = smc + FBBASE + m*BTILE;
#pragma unroll
            for (int i = 0; i < 2; i++) {
                const int q = tid + i*512;
                const int f = q >> 2, seg = q & 3;
                *(uint4*)(dst + f*BSTRIDE + seg*16) = src[q];
            }
        }
        __syncthreads();
#pragma unroll
        for (int kk = 0; kk < 2; kk++) {
            const uint32_t ak = aoff + (uint32_t)(kc*64 + kk*32);
            uint32_t aHh[4], aHl[4];
            ldsm4(ak,         aHh[0], aHh[1], aHh[2], aHh[3]);
            ldsm4(ak + ATILE, aHl[0], aHl[1], aHl[2], aHl[3]);
            uint32_t b[2][2][4];
            const uint32_t bk = boff + (uint32_t)(kk*32);
#pragma unroll
            for (int m = 0; m < 2; m++)
#pragma unroll
                for (int p = 0; p < 2; p++)
                    ldsm4(bk + m*BTILE + p*16*BSTRIDE,
                          b[m][p][0], b[m][p][1], b[m][p][2], b[m][p][3]);
#pragma unroll
            for (int nt = 0; nt < 4; nt++) {
                const int p = nt >> 1, s2 = nt & 1;
                const uint32_t bh0 = b[0][p][s2], bh1 = b[0][p][s2+2];
                const uint32_t bl0 = b[1][p][s2], bl1 = b[1][p][s2+2];
                mma_bf16(cm[nt], aHh, bh0, bh1);
                mma_bf16(cm[nt], aHh, bl0, bl1);
                mma_bf16(cm[nt], aHl, bh0, bh1);
            }
        }
    }

    // ---- epilogue ----
    const int r1 = lane >> 2, c2o = (lane & 3)*2;
    const int grow = tok0 + row0 + r1;
#pragma unroll
    for (int nt = 0; nt < 4; nt++) {
        const int col = col0 + nt*8 + c2o;
        const size_t o0 = (size_t)grow*256 + col;
        const size_t o1 = (size_t)(grow + 8)*256 + col;
        *(float2*)(out_means + o0) = make_float2(cm[nt][0], cm[nt][1]);
        *(float2*)(out_means + o1) = make_float2(cm[nt][2], cm[nt][3]);
        *(float2*)(out_stds  + o0) = make_float2(cs[nt][0], cs[nt][1]);
        *(float2*)(out_stds  + o1) = make_float2(cs[nt][2], cs[nt][3]);
    }
}

// ---------------- launch ----------------
extern "C" void kernel_launch(void* const* d_in, const int* in_sizes, int n_in,
                              void* d_out, int out_size) {
    const float* Z   = (const float*)d_in[0];
    const float* obs = (const float*)d_in[1];
    const float* D   = (const float*)d_in[2];
    const float* cW  = (const float*)d_in[3];
    const float* cb  = (const float*)d_in[4];
    const float* E_w = (const float*)d_in[5];
    const float* B_w = (const float*)d_in[6];
    const float* C_w = (const float*)d_in[7];
    const float* M_w = (const float*)d_in[8];
    const float* imp = (const float*)d_in[9];
    const float* ilv = (const float*)d_in[10];
    const float* ylv = (const float*)d_in[11];

    float* out        = (float*)d_out;
    float* out_means  = out;
    float* out_stds   = out + (size_t)BTn * LDn;
    float* out_alphas = out + 2 * (size_t)BTn * LDn;

    cudaFuncSetAttribute(k_token, cudaFuncAttributeMaxDynamicSharedMemorySize, SMEM_TOKEN);
    cudaFuncSetAttribute(k_fused, cudaFuncAttributeMaxDynamicSharedMemorySize, SMEM_OUT);

    k_pre_vec<<<64, 256>>>(E_w, D, imp, ilv, ylv);
    k_pre_bw<<<256, 256>>>(B_w);
    k_pre_gemm<<<dim3(8,8,2), dim3(32,32)>>>(E_w, M_w, C_w);
    k_token<<<BTn/32, 512, SMEM_TOKEN>>>(Z, obs, cW, cb, out_alphas);
    k_scan2<<<Bn, 512>>>();
    k_fused<<<BTn/32, 512, SMEM_OUT>>>(Z, out_alphas, out_means, out_stds);
}

// round 11
// speedup vs baseline: 1.6603x; 1.0287x over previous
#include <cuda_runtime.h>
#include <cuda_bf16.h>
#include <math.h>
#include <stdint.h>

#define EPSF 1e-6f
#define Bn 16
#define Tn 2048
#define LDn 256
#define NBn 32
#define BTn (Bn*Tn)
#define NCHUNK 64

typedef unsigned long long ull;

// ---------- warp-mma helpers ----------
static __device__ __forceinline__ uint32_t smem_u32(const void* p) {
    uint32_t a;
    asm("{ .reg .u64 t; cvta.to.shared.u64 t, %1; cvt.u32.u64 %0, t; }" : "=r"(a) : "l"(p));
    return a;
}
__device__ __forceinline__ void ldsm4(uint32_t addr, uint32_t& r0, uint32_t& r1,
                                      uint32_t& r2, uint32_t& r3) {
    asm volatile("ldmatrix.sync.aligned.m8n8.x4.shared.b16 {%0,%1,%2,%3}, [%4];"
                 : "=r"(r0), "=r"(r1), "=r"(r2), "=r"(r3) : "r"(addr));
}
__device__ __forceinline__ void mma_bf16(float* c, const uint32_t* a, uint32_t b0, uint32_t b1) {
    asm volatile(
        "mma.sync.aligned.m16n8k16.row.col.f32.bf16.bf16.f32 "
        "{%0,%1,%2,%3},{%4,%5,%6,%7},{%8,%9},{%0,%1,%2,%3};"
        : "+f"(c[0]), "+f"(c[1]), "+f"(c[2]), "+f"(c[3])
        : "r"(a[0]), "r"(a[1]), "r"(a[2]), "r"(a[3]), "r"(b0), "r"(b1));
}

// -------- scratch (device globals) --------
__device__ float2 g_eAiv[(size_t)BTn*LDn];   // (exp(A t), 1/A) packed
__device__ float g_aggA[Bn*NCHUNK*512];
__device__ float g_aggB[Bn*NCHUNK*512];
__device__ float g_carry[Bn*NCHUNK*512];
__device__ float g_Abasis[NBn*LDn];
__device__ float g_initmv[512];
__device__ float g_yvar[LDn];
// bf16 split weights, layout [kchunk(8)][row(256)][k(32)] per matrix
__device__ __align__(16) __nv_bfloat16 g_WMEh[65536];
__device__ __align__(16) __nv_bfloat16 g_WMEl[65536];
__device__ __align__(16) __nv_bfloat16 g_WCEh[65536];
__device__ __align__(16) __nv_bfloat16 g_WCEl[65536];
__device__ __align__(16) __nv_bfloat16 g_Bwh[65536];
__device__ __align__(16) __nv_bfloat16 g_Bwl[65536];

// ---------------- precompute: vectors (warp-per-output) + A_basis ----------------
__global__ void k_pre_vec(const float* __restrict__ E_w, const float* __restrict__ D,
                          const float* __restrict__ imp, const float* __restrict__ ilv,
                          const float* __restrict__ ylv) {
    const int tid = threadIdx.x, lane = tid & 31;
    const int w = blockIdx.x*8 + (tid >> 5);
    float s = 0.f;
    if (w < 256) {
#pragma unroll
        for (int j = 0; j < 8; j++) { int k = lane + 32*j; s = fmaf(E_w[k*256 + w], imp[k], s); }
    } else {
        const int i = w - 256;
#pragma unroll
        for (int j = 0; j < 8; j++) {
            int k = lane + 32*j; float e = E_w[k*256 + i];
            s = fmaf(e*e, expf(ilv[k]) + EPSF, s);
        }
    }
#pragma unroll
    for (int off = 16; off > 0; off >>= 1) s += __shfl_xor_sync(0xffffffffu, s, off);
    if (lane == 0) {
        g_initmv[w] = s;
        if (w < 256) g_yvar[w] = expf(ylv[w]) + EPSF;
    }
    const int gid = blockIdx.x*256 + tid;
    if (gid < NBn*LDn) g_Abasis[gid] = -(expf(D[gid]) + EPSF);
}

// ---------------- precompute: B_w bf16 split, [kc][e][kk] ----------------
__global__ void k_pre_bw(const float* __restrict__ B_w) {
    const int e = blockIdx.x, d = threadIdx.x;
    const float v = B_w[e*256 + d];
    __nv_bfloat16 h = __float2bfloat16(v);
    __nv_bfloat16 l = __float2bfloat16(v - __bfloat162float(h));
    const int idx = (d >> 5)*8192 + e*32 + (d & 31);
    g_Bwh[idx] = h;
    g_Bwl[idx] = l;
}

// ---------------- precompute: W_ME/W_CE bf16 splits, [kc][f][kk] ----------------
__global__ void k_pre_gemm(const float* __restrict__ E_w, const float* __restrict__ M_w,
                           const float* __restrict__ C_w) {
    const float* X = (blockIdx.z == 0) ? M_w : C_w;
    __nv_bfloat16* oh = (blockIdx.z == 0) ? g_WMEh : g_WCEh;
    __nv_bfloat16* ol = (blockIdx.z == 0) ? g_WMEl : g_WCEl;
    __shared__ float sE[32][33];
    __shared__ float sX[32][33];
    const int tx = threadIdx.x, ty = threadIdx.y;
    const int d0 = blockIdx.x*32, f0 = blockIdx.y*32;
    float acc = 0.f;
    for (int e0 = 0; e0 < 256; e0 += 32) {
        sE[ty][tx] = E_w[(e0+ty)*256 + d0 + tx];
        sX[ty][tx] = X[(f0+ty)*256 + e0 + tx];
        __syncthreads();
#pragma unroll
        for (int e = 0; e < 32; e++) acc = fmaf(sE[e][ty], sX[tx][e], acc);
        __syncthreads();
    }
    const int f = f0 + tx, d = d0 + ty;
    __nv_bfloat16 h = __float2bfloat16(acc);
    __nv_bfloat16 l = __float2bfloat16(acc - __bfloat162float(h));
    const int idx = (d >> 5)*8192 + f*32 + (d & 31);
    oh[idx] = h;
    ol[idx] = l;
}

// ---------------- shared tile geometry ----------------
#define ASTRIDE 528
#define ATILE   16896
#define BSTRIDE 80
#define BTILE   20480

__device__ __forceinline__ void put_split(char* hB, char* lB, int r, int d, float v) {
    __nv_bfloat16 h = __float2bfloat16(v);
    __nv_bfloat16 l = __float2bfloat16(v - __bfloat162float(h));
    const uint32_t off = (uint32_t)r*ASTRIDE + (uint32_t)d*2;
    *(__nv_bfloat16*)(hB + off) = h;
    *(__nv_bfloat16*)(lB + off) = l;
}

// vectorized: 4 consecutive d's, one 8B store per tile
__device__ __forceinline__ void put_split4(char* hB, char* lB, int r, int d4, float4 v) {
    ull hp = 0, lp = 0;
    const float vv[4] = { v.x, v.y, v.z, v.w };
#pragma unroll
    for (int j = 0; j < 4; j++) {
        __nv_bfloat16 h = __float2bfloat16(vv[j]);
        __nv_bfloat16 l = __float2bfloat16(vv[j] - __bfloat162float(h));
        hp |= (ull)__bfloat16_as_ushort(h) << (16*j);
        lp |= (ull)__bfloat16_as_ushort(l) << (16*j);
    }
    const uint32_t off = (uint32_t)r*ASTRIDE + (uint32_t)d4*2;
    *(ull*)(hB + off) = hp;
    *(ull*)(lB + off) = lp;
}

// ---------------- k_token ----------------
// A area [0, 33792): Z hi/lo tiles; later sCW (32x260 f32 = 33280) then sPar (8x256 f32)
// B area [33792, 74752): B staging hi/lo; later sAL (32x256 f32)
// sCoefT at 74752 (32n x 36 f32 = 4608), sT at 79360
#define TBBASE   33792
#define TCOEF    74752
#define TTIME    79360
#define SMEM_TOKEN (TTIME + 128)
__global__ void __launch_bounds__(512, 2) k_token(const float* __restrict__ Z,
        const float* __restrict__ obs, const float* __restrict__ cW,
        const float* __restrict__ cb, float* __restrict__ alphas_out) {
    extern __shared__ char smc[];
    const uint32_t sbase = smem_u32(smc);
    float* sCoefT = (float*)(smc + TCOEF);
    float* sT     = (float*)(smc + TTIME);
    const int tid = threadIdx.x;
    const int bc = blockIdx.x;
    const int tok0 = bc * 32;

    // ---- phase 1: Z -> bf16 split tiles (float4 / 8B stores) ----
    {
#pragma unroll
        for (int it = 0; it < 4; it++) {
            const int q = tid + it*512;          // 0..2047 = 32 r x 64 d4
            const int r = q >> 6, d4 = (q & 63) * 4;
            const float4 z4 = *(const float4*)(Z + (size_t)(tok0 + r)*256 + d4);
            put_split4(smc, smc + ATILE, r, d4, z4);
        }
        if (tid < 32) sT[tid] = obs[tok0 + tid];
    }

    // ---- phase 2: alphas = Z @ B_w^T via 3-term split mma ----
    const int lane = tid & 31, wid = tid >> 5;
    const int row0 = (wid & 1) * 16;
    const int col0 = (wid >> 1) * 32;
    float cm[4][4];
#pragma unroll
    for (int nt = 0; nt < 4; nt++)
#pragma unroll
        for (int q = 0; q < 4; q++) cm[nt][q] = 0.f;

    const uint32_t aoff = sbase + (uint32_t)(row0 + (lane & 15))*ASTRIDE + (uint32_t)(lane >> 4)*16;
    const uint32_t boff = sbase + TBBASE + (uint32_t)(col0 + (lane & 15))*BSTRIDE + (uint32_t)(lane >> 4)*16;

    for (int kc = 0; kc < 8; kc++) {
        __syncthreads();
#pragma unroll
        for (int m = 0; m < 2; m++) {
            const uint4* src = ((m == 0) ? (const uint4*)g_Bwh : (const uint4*)g_Bwl) + kc*1024;
            char* dst = smc + TBBASE + m*BTILE;
#pragma unroll
            for (int i = 0; i < 2; i++) {
                const int q = tid + i*512;
                const int f = q >> 2, seg = q & 3;
                *(uint4*)(dst + f*BSTRIDE + seg*16) = src[q];
            }
        }
        __syncthreads();
#pragma unroll
        for (int kk = 0; kk < 2; kk++) {
            const uint32_t ak = aoff + (uint32_t)(kc*64 + kk*32);
            uint32_t aZh[4], aZl[4];
            ldsm4(ak,         aZh[0], aZh[1], aZh[2], aZh[3]);
            ldsm4(ak + ATILE, aZl[0], aZl[1], aZl[2], aZl[3]);
            uint32_t b[2][2][4];
            const uint32_t bk = boff + (uint32_t)(kk*32);
#pragma unroll
            for (int m = 0; m < 2; m++)
#pragma unroll
                for (int p = 0; p < 2; p++)
                    ldsm4(bk + m*BTILE + p*16*BSTRIDE,
                          b[m][p][0], b[m][p][1], b[m][p][2], b[m][p][3]);
#pragma unroll
            for (int nt = 0; nt < 4; nt++) {
                const int p = nt >> 1, s2 = nt & 1;
                const uint32_t bh0 = b[0][p][s2], bh1 = b[0][p][s2+2];
                const uint32_t bl0 = b[1][p][s2], bl1 = b[1][p][s2+2];
                mma_bf16(cm[nt], aZh, bh0, bh1);
                mma_bf16(cm[nt], aZh, bl0, bl1);
                mma_bf16(cm[nt], aZl, bh0, bh1);
            }
        }
    }
    __syncthreads();

    // ---- epilogue: alphas -> sAL (B area) + gmem; cW -> sCW (A area, pad 260) ----
    float* sAL = (float*)(smc + TBBASE);
    float* sCW = (float*)smc;
    {
        const int r1 = lane >> 2, c2o = (lane & 3)*2;
#pragma unroll
        for (int nt = 0; nt < 4; nt++) {
            const int col = col0 + nt*8 + c2o;
            const int lr0 = row0 + r1, lr1 = row0 + r1 + 8;
            sAL[lr0*256 + col]     = cm[nt][0];
            sAL[lr0*256 + col + 1] = cm[nt][1];
            sAL[lr1*256 + col]     = cm[nt][2];
            sAL[lr1*256 + col + 1] = cm[nt][3];
            *(float2*)(alphas_out + (size_t)(tok0+lr0)*256 + col) = make_float2(cm[nt][0], cm[nt][1]);
            *(float2*)(alphas_out + (size_t)(tok0+lr1)*256 + col) = make_float2(cm[nt][2], cm[nt][3]);
        }
        for (int idx = tid; idx < 32*256; idx += 512)
            sCW[(idx >> 8)*260 + (idx & 255)] = cW[idx];
    }
    __syncthreads();

    // ---- phase 3: logits + softmax (all-float4 LDS) ----
#pragma unroll
    for (int rr = 0; rr < 2; rr++) {
        const int r = wid*2 + rr;
        const float4* arow = (const float4*)(sAL + r*256);
        const float4* crow = (const float4*)(sCW + lane*260);
        float lg = cb[lane];
#pragma unroll 8
        for (int q = 0; q < 64; q++) {
            const float4 a4 = arow[q];
            const float4 c4 = crow[q];
            lg = fmaf(a4.x, c4.x, lg);
            lg = fmaf(a4.y, c4.y, lg);
            lg = fmaf(a4.z, c4.z, lg);
            lg = fmaf(a4.w, c4.w, lg);
        }
        float m = lg;
#pragma unroll
        for (int off = 16; off > 0; off >>= 1)
            m = fmaxf(m, __shfl_xor_sync(0xffffffffu, m, off));
        const float e = __expf(lg - m);
        float s = e;
#pragma unroll
        for (int off = 16; off > 0; off >>= 1)
            s += __shfl_xor_sync(0xffffffffu, s, off);
        sCoefT[lane*36 + r] = e / s;     // transposed: [n][token]
    }
    __syncthreads();

    // ---- phase 4: A_mat + exp terms + half-chunk aggregates (float4 coeff reads) ----
    const int c = tid & 255;
    const int h = tid >> 8;
    const int rbase = h * 16;
    float am[16];
#pragma unroll
    for (int rr = 0; rr < 16; rr++) am[rr] = 0.f;
#pragma unroll 4
    for (int n = 0; n < 32; n++) {
        const float ab = g_Abasis[n*256 + c];
        const float4* cp = (const float4*)(sCoefT + n*36 + rbase);
#pragma unroll
        for (int j4 = 0; j4 < 4; j4++) {
            const float4 cc = cp[j4];
            am[j4*4+0] = fmaf(cc.x, ab, am[j4*4+0]);
            am[j4*4+1] = fmaf(cc.y, ab, am[j4*4+1]);
            am[j4*4+2] = fmaf(cc.z, ab, am[j4*4+2]);
            am[j4*4+3] = fmaf(cc.w, ab, am[j4*4+3]);
        }
    }
    float aAm = 1.f, bBm = 0.f, aAv = 1.f, bBv = 0.f;
#pragma unroll 4
    for (int rr = 0; rr < 16; rr++) {
        const int r = rbase + rr;
        const float a = am[rr];
        const float t = sT[r];
        const float eAm = __expf(a * t);
        const float inv = __fdividef(1.0f, a);
        const float al  = sAL[r*256 + c];
        const float eBm = (eAm - 1.f) * inv * al;
        const float eAv = eAm * eAm;
        const float eBv = 0.5f*(eAv - 1.f)*inv + EPSF;
        const size_t o = (size_t)(tok0 + r)*256 + c;
        g_eAiv[o] = make_float2(eAm, inv);
        bBm = fmaf(eAm, bBm, eBm); aAm *= eAm;
        bBv = fmaf(eAv, bBv, eBv); aAv *= eAv;
    }
    float* sPar = (float*)smc;
    sPar[(h*4+0)*256 + c] = aAm;
    sPar[(h*4+1)*256 + c] = bBm;
    sPar[(h*4+2)*256 + c] = aAv;
    sPar[(h*4+3)*256 + c] = bBv;
    __syncthreads();
    if (tid < 256) {
        const float A0m = sPar[tid],        B0m = sPar[256 + tid];
        const float A0v = sPar[512 + tid],  B0v = sPar[768 + tid];
        const float A1m = sPar[1024 + tid], B1m = sPar[1280 + tid];
        const float A1v = sPar[1536 + tid], B1v = sPar[1792 + tid];
        g_aggA[bc*512 + tid]       = A1m * A0m;
        g_aggB[bc*512 + tid]       = fmaf(A1m, B0m, B1m);
        g_aggA[bc*512 + 256 + tid] = A1v * A0v;
        g_aggB[bc*512 + 256 + tid] = fmaf(A1v, B0v, B1v);
    }
}

// ---------------- scan over chunk aggregates ----------------
__global__ void k_scan2() {
    const int b = blockIdx.x;
    const int c = threadIdx.x;
    float s = g_initmv[c];
#pragma unroll 4
    for (int j = 0; j < NCHUNK; j++) {
        const int idx = (b*NCHUNK + j)*512 + c;
        g_carry[idx] = s;
        s = fmaf(g_aggA[idx], s, g_aggB[idx]);
    }
}

// ---------------- k_fused: two-pass scan-apply + warp-mma output GEMMs ----------------
#define FBBASE   (4*ATILE)
#define SMEM_OUT (FBBASE + 2*BTILE)

__global__ void __launch_bounds__(512, 2) k_fused(const float* __restrict__ Z,
        const float* __restrict__ alphas,
        float* __restrict__ out_means, float* __restrict__ out_stds) {
    extern __shared__ char smc[];
    const uint32_t sbase = smem_u32(smc);
    const int tid = threadIdx.x;
    const int bc = blockIdx.x;
    const int tok0 = bc * 32;

    // ---- phase 1a: scan apply -> X (mean) and V (std) split tiles ----
    {
        const int d = tid & 255;
        if (tid < 256) {
            float s = g_carry[bc*512 + d];
#pragma unroll 4
            for (int r = 0; r < 32; r++) {
                const size_t o = (size_t)(tok0 + r)*256 + d;
                const float2 ei = g_eAiv[o];
                const float al = alphas[o];
                s = fmaf(ei.x, s, (ei.x - 1.f)*ei.y*al);
                put_split(smc, smc + ATILE, r, d, s);
            }
        } else {
            float s = g_carry[bc*512 + 256 + d];
            const float yv = g_yvar[d];
#pragma unroll 4
            for (int r = 0; r < 32; r++) {
                const size_t o = (size_t)(tok0 + r)*256 + d;
                const float2 ei = g_eAiv[o];
                const float eAv = ei.x * ei.x;
                s = fmaf(eAv, s, 0.5f*(eAv - 1.f)*ei.y + EPSF);
                put_split(smc + 2*ATILE, smc + 3*ATILE, r, d, sqrtf(s + yv));
            }
        }
    }

    const int lane = tid & 31, wid = tid >> 5;
    const int row0 = (wid & 1) * 16;
    const int col0 = (wid >> 1) * 32;
    float cm[4][4], cs[4][4];
#pragma unroll
    for (int nt = 0; nt < 4; nt++)
#pragma unroll
        for (int q = 0; q < 4; q++) { cm[nt][q] = 0.f; cs[nt][q] = 0.f; }

    const uint32_t aoff = sbase + (uint32_t)(row0 + (lane & 15))*ASTRIDE + (uint32_t)(lane >> 4)*16;
    const uint32_t boff = sbase + FBBASE + (uint32_t)(col0 + (lane & 15))*BSTRIDE + (uint32_t)(lane >> 4)*16;

    // ---- pass A: WME against X (means) and V (stds) ----
    for (int kc = 0; kc < 8; kc++) {
        __syncthreads();
#pragma unroll
        for (int m = 0; m < 2; m++) {
            const uint4* src = ((m == 0) ? (const uint4*)g_WMEh : (const uint4*)g_WMEl) + kc*1024;
            char* dst = smc + FBBASE + m*BTILE;
#pragma unroll
            for (int i = 0; i < 2; i++) {
                const int q = tid + i*512;
                const int f = q >> 2, seg = q & 3;
                *(uint4*)(dst + f*BSTRIDE + seg*16) = src[q];
            }
        }
        __syncthreads();
#pragma unroll
        for (int kk = 0; kk < 2; kk++) {
            const uint32_t ak = aoff + (uint32_t)(kc*64 + kk*32);
            uint32_t aXh[4], aXl[4], aVh[4], aVl[4];
            ldsm4(ak,           aXh[0], aXh[1], aXh[2], aXh[3]);
            ldsm4(ak + ATILE,   aXl[0], aXl[1], aXl[2], aXl[3]);
            ldsm4(ak + 2*ATILE, aVh[0], aVh[1], aVh[2], aVh[3]);
            ldsm4(ak + 3*ATILE, aVl[0], aVl[1], aVl[2], aVl[3]);
            uint32_t b[2][2][4];
            const uint32_t bk = boff + (uint32_t)(kk*32);
#pragma unroll
            for (int m = 0; m < 2; m++)
#pragma unroll
                for (int p = 0; p < 2; p++)
                    ldsm4(bk + m*BTILE + p*16*BSTRIDE,
                          b[m][p][0], b[m][p][1], b[m][p][2], b[m][p][3]);
#pragma unroll
            for (int nt = 0; nt < 4; nt++) {
                const int p = nt >> 1, s2 = nt & 1;
                const uint32_t bh0 = b[0][p][s2], bh1 = b[0][p][s2+2];
                const uint32_t bl0 = b[1][p][s2], bl1 = b[1][p][s2+2];
                mma_bf16(cm[nt], aXh, bh0, bh1);
                mma_bf16(cm[nt], aXh, bl0, bl1);
                mma_bf16(cm[nt], aXl, bh0, bh1);
                mma_bf16(cs[nt], aVh, bh0, bh1);
                mma_bf16(cs[nt], aVh, bl0, bl1);
                mma_bf16(cs[nt], aVl, bh0, bh1);
            }
        }
    }
    __syncthreads();

    // ---- phase 1b: H = Z -> tiles 0,1 (aliasing X), float4 ----
    {
#pragma unroll
        for (int it = 0; it < 4; it++) {
            const int q = tid + it*512;
            const int r = q >> 6, d4 = (q & 63) * 4;
            const float4 z4 = *(const float4*)(Z + (size_t)(tok0 + r)*256 + d4);
            put_split4(smc, smc + ATILE, r, d4, z4);
        }
    }

    // ---- pass B: WCE against H (means accumulate) ----
    for (int kc = 0; kc < 8; kc++) {
        __syncthreads();
#pragma unroll
        for (int m = 0; m < 2; m++) {
            const uint4* src = ((m == 0) ? (const uint4*)g_WCEh : (const uint4*)g_WCEl) + kc*1024;
            char* dst = smc + FBBASE + m*BTILE;
#pragma unroll
            for (int i = 0; i < 2; i++) {
                const int q = tid + i*512;
                const int f = q >> 2, seg = q & 3;
                *(uint4*)(dst + f*BSTRIDE + seg*16) = src[q];
            }
        }
        __syncthreads();
#pragma unroll
        for (int kk = 0; kk < 2; kk++) {
            const uint32_t ak = aoff + (uint32_t)(kc*64 + kk*32);
            uint32_t aHh[4], aHl[4];
            ldsm4(ak,         aHh[0], aHh[1], aHh[2], aHh[3]);
            ldsm4(ak + ATILE, aHl[0], aHl[1], aHl[2], aHl[3]);
            uint32_t b[2][2][4];
            const uint32_t bk = boff + (uint32_t)(kk*32);
#pragma unroll
            for (int m = 0; m < 2; m++)
#pragma unroll
                for (int p = 0; p < 2; p++)
                    ldsm4(bk + m*BTILE + p*16*BSTRIDE,
                          b[m][p][0], b[m][p][1], b[m][p][2], b[m][p][3]);
#pragma unroll
            for (int nt = 0; nt < 4; nt++) {
                const int p = nt >> 1, s2 = nt & 1;
                const uint32_t bh0 = b[0][p][s2], bh1 = b[0][p][s2+2];
                const uint32_t bl0 = b[1][p][s2], bl1 = b[1][p][s2+2];
                mma_bf16(cm[nt], aHh, bh0, bh1);
                mma_bf16(cm[nt], aHh, bl0, bl1);
                mma_bf16(cm[nt], aHl, bh0, bh1);
            }
        }
    }

    // ---- epilogue ----
    const int r1 = lane >> 2, c2o = (lane & 3)*2;
    const int grow = tok0 + row0 + r1;
#pragma unroll
    for (int nt = 0; nt < 4; nt++) {
        const int col = col0 + nt*8 + c2o;
        const size_t o0 = (size_t)grow*256 + col;
        const size_t o1 = (size_t)(grow + 8)*256 + col;
        *(float2*)(out_means + o0) = make_float2(cm[nt][0], cm[nt][1]);
        *(float2*)(out_means + o1) = make_float2(cm[nt][2], cm[nt][3]);
        *(float2*)(out_stds  + o0) = make_float2(cs[nt][0], cs[nt][1]);
        *(float2*)(out_stds  + o1) = make_float2(cs[nt][2], cs[nt][3]);
    }
}

// ---------------- launch ----------------
extern "C" void kernel_launch(void* const* d_in, const int* in_sizes, int n_in,
                              void* d_out, int out_size) {
    const float* Z   = (const float*)d_in[0];
    const float* obs = (const float*)d_in[1];
    const float* D   = (const float*)d_in[2];
    const float* cW  = (const float*)d_in[3];
    const float* cb  = (const float*)d_in[4];
    const float* E_w = (const float*)d_in[5];
    const float* B_w = (const float*)d_in[6];
    const float* C_w = (const float*)d_in[7];
    const float* M_w = (const float*)d_in[8];
    const float* imp = (const float*)d_in[9];
    const float* ilv = (const float*)d_in[10];
    const float* ylv = (const float*)d_in[11];

    float* out        = (float*)d_out;
    float* out_means  = out;
    float* out_stds   = out + (size_t)BTn * LDn;
    float* out_alphas = out + 2 * (size_t)BTn * LDn;

    cudaFuncSetAttribute(k_token, cudaFuncAttributeMaxDynamicSharedMemorySize, SMEM_TOKEN);
    cudaFuncSetAttribute(k_fused, cudaFuncAttributeMaxDynamicSharedMemorySize, SMEM_OUT);

    k_pre_vec<<<64, 256>>>(E_w, D, imp, ilv, ylv);
    k_pre_bw<<<256, 256>>>(B_w);
    k_pre_gemm<<<dim3(8,8,2), dim3(32,32)>>>(E_w, M_w, C_w);
    k_token<<<BTn/32, 512, SMEM_TOKEN>>>(Z, obs, cW, cb, out_alphas);
    k_scan2<<<Bn, 512>>>();
    k_fused<<<BTn/32, 512, SMEM_OUT>>>(Z, out_alphas, out_means, out_stds);
}

// round 12
// speedup vs baseline: 1.7739x; 1.0684x over previous
#include <cuda_runtime.h>
#include <cuda_bf16.h>
#include <math.h>
#include <stdint.h>

#define EPSF 1e-6f
#define Bn 16
#define Tn 2048
#define LDn 256
#define NBn 32
#define BTn (Bn*Tn)
#define NCHUNK 64

typedef unsigned long long ull;

// ---------- warp-mma helpers ----------
static __device__ __forceinline__ uint32_t smem_u32(const void* p) {
    uint32_t a;
    asm("{ .reg .u64 t; cvta.to.shared.u64 t, %1; cvt.u32.u64 %0, t; }" : "=r"(a) : "l"(p));
    return a;
}
__device__ __forceinline__ void ldsm4(uint32_t addr, uint32_t& r0, uint32_t& r1,
                                      uint32_t& r2, uint32_t& r3) {
    asm volatile("ldmatrix.sync.aligned.m8n8.x4.shared.b16 {%0,%1,%2,%3}, [%4];"
                 : "=r"(r0), "=r"(r1), "=r"(r2), "=r"(r3) : "r"(addr));
}
__device__ __forceinline__ void mma_bf16(float* c, const uint32_t* a, uint32_t b0, uint32_t b1) {
    asm volatile(
        "mma.sync.aligned.m16n8k16.row.col.f32.bf16.bf16.f32 "
        "{%0,%1,%2,%3},{%4,%5,%6,%7},{%8,%9},{%0,%1,%2,%3};"
        : "+f"(c[0]), "+f"(c[1]), "+f"(c[2]), "+f"(c[3])
        : "r"(a[0]), "r"(a[1]), "r"(a[2]), "r"(a[3]), "r"(b0), "r"(b1));
}

// -------- scratch (device globals) --------
__device__ float2 g_eAiv[(size_t)BTn*LDn];   // (exp(A t), 1/A) packed
__device__ float g_aggA[Bn*NCHUNK*512];
__device__ float g_aggB[Bn*NCHUNK*512];
__device__ float g_carry[Bn*NCHUNK*512];
__device__ float g_Abasis[NBn*LDn];
__device__ float g_initmv[512];
__device__ float g_yvar[LDn];
// bf16 split weights, layout [kchunk(8)][row(256)][k(32)] per matrix
__device__ __align__(16) __nv_bfloat16 g_WMEh[65536];
__device__ __align__(16) __nv_bfloat16 g_WMEl[65536];
__device__ __align__(16) __nv_bfloat16 g_WCEh[65536];
__device__ __align__(16) __nv_bfloat16 g_WCEl[65536];
__device__ __align__(16) __nv_bfloat16 g_Bwh[65536];
__device__ __align__(16) __nv_bfloat16 g_Bwl[65536];

// ---------------- precompute: vectors + A_basis + B_w split (merged) ----------------
__global__ void k_pre_misc(const float* __restrict__ E_w, const float* __restrict__ D,
                           const float* __restrict__ imp, const float* __restrict__ ilv,
                           const float* __restrict__ ylv, const float* __restrict__ B_w) {
    const int tid = threadIdx.x;
    if (blockIdx.x < 64) {
        const int lane = tid & 31;
        const int w = blockIdx.x*8 + (tid >> 5);
        float s = 0.f;
        if (w < 256) {
#pragma unroll
            for (int j = 0; j < 8; j++) { int k = lane + 32*j; s = fmaf(E_w[k*256 + w], imp[k], s); }
        } else {
            const int i = w - 256;
#pragma unroll
            for (int j = 0; j < 8; j++) {
                int k = lane + 32*j; float e = E_w[k*256 + i];
                s = fmaf(e*e, expf(ilv[k]) + EPSF, s);
            }
        }
#pragma unroll
        for (int off = 16; off > 0; off >>= 1) s += __shfl_xor_sync(0xffffffffu, s, off);
        if (lane == 0) {
            g_initmv[w] = s;
            if (w < 256) g_yvar[w] = expf(ylv[w]) + EPSF;
        }
        const int gid = blockIdx.x*256 + tid;
        if (gid < NBn*LDn) g_Abasis[gid] = -(expf(D[gid]) + EPSF);
    } else {
        const int e = blockIdx.x - 64, d = tid;
        const float v = B_w[e*256 + d];
        __nv_bfloat16 h = __float2bfloat16(v);
        __nv_bfloat16 l = __float2bfloat16(v - __bfloat162float(h));
        const int idx = (d >> 5)*8192 + e*32 + (d & 31);
        g_Bwh[idx] = h;
        g_Bwl[idx] = l;
    }
}

// ---------------- precompute: W_ME/W_CE bf16 splits, [kc][f][kk] ----------------
__global__ void k_pre_gemm(const float* __restrict__ E_w, const float* __restrict__ M_w,
                           const float* __restrict__ C_w) {
    const float* X = (blockIdx.z == 0) ? M_w : C_w;
    __nv_bfloat16* oh = (blockIdx.z == 0) ? g_WMEh : g_WCEh;
    __nv_bfloat16* ol = (blockIdx.z == 0) ? g_WMEl : g_WCEl;
    __shared__ float sE[32][33];
    __shared__ float sX[32][33];
    const int tx = threadIdx.x, ty = threadIdx.y;
    const int d0 = blockIdx.x*32, f0 = blockIdx.y*32;
    float acc = 0.f;
    for (int e0 = 0; e0 < 256; e0 += 32) {
        sE[ty][tx] = E_w[(e0+ty)*256 + d0 + tx];
        sX[ty][tx] = X[(f0+ty)*256 + e0 + tx];
        __syncthreads();
#pragma unroll
        for (int e = 0; e < 32; e++) acc = fmaf(sE[e][ty], sX[tx][e], acc);
        __syncthreads();
    }
    const int f = f0 + tx, d = d0 + ty;
    __nv_bfloat16 h = __float2bfloat16(acc);
    __nv_bfloat16 l = __float2bfloat16(acc - __bfloat162float(h));
    const int idx = (d >> 5)*8192 + f*32 + (d & 31);
    oh[idx] = h;
    ol[idx] = l;
}

// ---------------- shared tile geometry ----------------
#define ASTRIDE 528
#define ATILE   16896
#define BSTRIDE 80
#define BTILE   20480

__device__ __forceinline__ void put_split(char* hB, char* lB, int r, int d, float v) {
    __nv_bfloat16 h = __float2bfloat16(v);
    __nv_bfloat16 l = __float2bfloat16(v - __bfloat162float(h));
    const uint32_t off = (uint32_t)r*ASTRIDE + (uint32_t)d*2;
    *(__nv_bfloat16*)(hB + off) = h;
    *(__nv_bfloat16*)(lB + off) = l;
}

// vectorized: 4 consecutive d's, one 8B store per tile
__device__ __forceinline__ void put_split4(char* hB, char* lB, int r, int d4, float4 v) {
    ull hp = 0, lp = 0;
    const float vv[4] = { v.x, v.y, v.z, v.w };
#pragma unroll
    for (int j = 0; j < 4; j++) {
        __nv_bfloat16 h = __float2bfloat16(vv[j]);
        __nv_bfloat16 l = __float2bfloat16(vv[j] - __bfloat162float(h));
        hp |= (ull)__bfloat16_as_ushort(h) << (16*j);
        lp |= (ull)__bfloat16_as_ushort(l) << (16*j);
    }
    const uint32_t off = (uint32_t)r*ASTRIDE + (uint32_t)d4*2;
    *(ull*)(hB + off) = hp;
    *(ull*)(lB + off) = lp;
}

// ---------------- k_token ----------------
// A area [0, 33792): Z hi/lo tiles; later sCW (32x260 f32 = 33280) then sPar (8x256 f32)
// B area [33792, 74752): B staging hi/lo; later sAL (32x256 f32)
// sCoefT at 74752 (32n x 36 f32 = 4608), sT at 79360
#define TBBASE   33792
#define TCOEF    74752
#define TTIME    79360
#define SMEM_TOKEN (TTIME + 128)
__global__ void __launch_bounds__(512, 2) k_token(const float* __restrict__ Z,
        const float* __restrict__ obs, const float* __restrict__ cW,
        const float* __restrict__ cb, float* __restrict__ alphas_out) {
    extern __shared__ char smc[];
    const uint32_t sbase = smem_u32(smc);
    float* sCoefT = (float*)(smc + TCOEF);
    float* sT     = (float*)(smc + TTIME);
    const int tid = threadIdx.x;
    const int bc = blockIdx.x;
    const int tok0 = bc * 32;

    // ---- phase 1: Z -> bf16 split tiles (float4 / 8B stores) ----
    {
#pragma unroll
        for (int it = 0; it < 4; it++) {
            const int q = tid + it*512;          // 0..2047 = 32 r x 64 d4
            const int r = q >> 6, d4 = (q & 63) * 4;
            const float4 z4 = *(const float4*)(Z + (size_t)(tok0 + r)*256 + d4);
            put_split4(smc, smc + ATILE, r, d4, z4);
        }
        if (tid < 32) sT[tid] = obs[tok0 + tid];
    }

    // ---- phase 2: alphas = Z @ B_w^T via 3-term split mma ----
    const int lane = tid & 31, wid = tid >> 5;
    const int row0 = (wid & 1) * 16;
    const int col0 = (wid >> 1) * 32;
    float cm[4][4];
#pragma unroll
    for (int nt = 0; nt < 4; nt++)
#pragma unroll
        for (int q = 0; q < 4; q++) cm[nt][q] = 0.f;

    const uint32_t aoff = sbase + (uint32_t)(row0 + (lane & 15))*ASTRIDE + (uint32_t)(lane >> 4)*16;
    const uint32_t boff = sbase + TBBASE + (uint32_t)(col0 + (lane & 15))*BSTRIDE + (uint32_t)(lane >> 4)*16;

    for (int kc = 0; kc < 8; kc++) {
        __syncthreads();
#pragma unroll
        for (int m = 0; m < 2; m++) {
            const uint4* src = ((m == 0) ? (const uint4*)g_Bwh : (const uint4*)g_Bwl) + kc*1024;
            char* dst = smc + TBBASE + m*BTILE;
#pragma unroll
            for (int i = 0; i < 2; i++) {
                const int q = tid + i*512;
                const int f = q >> 2, seg = q & 3;
                *(uint4*)(dst + f*BSTRIDE + seg*16) = src[q];
            }
        }
        __syncthreads();
#pragma unroll
        for (int kk = 0; kk < 2; kk++) {
            const uint32_t ak = aoff + (uint32_t)(kc*64 + kk*32);
            uint32_t aZh[4], aZl[4];
            ldsm4(ak,         aZh[0], aZh[1], aZh[2], aZh[3]);
            ldsm4(ak + ATILE, aZl[0], aZl[1], aZl[2], aZl[3]);
            uint32_t b[2][2][4];
            const uint32_t bk = boff + (uint32_t)(kk*32);
#pragma unroll
            for (int m = 0; m < 2; m++)
#pragma unroll
                for (int p = 0; p < 2; p++)
                    ldsm4(bk + m*BTILE + p*16*BSTRIDE,
                          b[m][p][0], b[m][p][1], b[m][p][2], b[m][p][3]);
#pragma unroll
            for (int nt = 0; nt < 4; nt++) {
                const int p = nt >> 1, s2 = nt & 1;
                const uint32_t bh0 = b[0][p][s2], bh1 = b[0][p][s2+2];
                const uint32_t bl0 = b[1][p][s2], bl1 = b[1][p][s2+2];
                mma_bf16(cm[nt], aZh, bh0, bh1);
                mma_bf16(cm[nt], aZh, bl0, bl1);
                mma_bf16(cm[nt], aZl, bh0, bh1);
            }
        }
    }
    __syncthreads();

    // ---- epilogue: alphas -> sAL (B area) + gmem; cW -> sCW (A area, pad 260) ----
    float* sAL = (float*)(smc + TBBASE);
    float* sCW = (float*)smc;
    {
        const int r1 = lane >> 2, c2o = (lane & 3)*2;
#pragma unroll
        for (int nt = 0; nt < 4; nt++) {
            const int col = col0 + nt*8 + c2o;
            const int lr0 = row0 + r1, lr1 = row0 + r1 + 8;
            sAL[lr0*256 + col]     = cm[nt][0];
            sAL[lr0*256 + col + 1] = cm[nt][1];
            sAL[lr1*256 + col]     = cm[nt][2];
            sAL[lr1*256 + col + 1] = cm[nt][3];
            *(float2*)(alphas_out + (size_t)(tok0+lr0)*256 + col) = make_float2(cm[nt][0], cm[nt][1]);
            *(float2*)(alphas_out + (size_t)(tok0+lr1)*256 + col) = make_float2(cm[nt][2], cm[nt][3]);
        }
        for (int idx = tid; idx < 32*256; idx += 512)
            sCW[(idx >> 8)*260 + (idx & 255)] = cW[idx];
    }
    __syncthreads();

    // ---- phase 3: logits + softmax (8 warps x 4 tokens, lane = basis n) ----
    if (wid < 8) {
        const int t0 = wid * 4;
        const float4* crow = (const float4*)(sCW + lane*260);
        const float4* a0 = (const float4*)(sAL + (t0+0)*256);
        const float4* a1 = (const float4*)(sAL + (t0+1)*256);
        const float4* a2 = (const float4*)(sAL + (t0+2)*256);
        const float4* a3 = (const float4*)(sAL + (t0+3)*256);
        const float bias = cb[lane];
        float lg0 = bias, lg1 = bias, lg2 = bias, lg3 = bias;
#pragma unroll 4
        for (int q = 0; q < 64; q++) {
            const float4 c4 = crow[q];
            const float4 v0 = a0[q];
            lg0 = fmaf(v0.x, c4.x, lg0); lg0 = fmaf(v0.y, c4.y, lg0);
            lg0 = fmaf(v0.z, c4.z, lg0); lg0 = fmaf(v0.w, c4.w, lg0);
            const float4 v1 = a1[q];
            lg1 = fmaf(v1.x, c4.x, lg1); lg1 = fmaf(v1.y, c4.y, lg1);
            lg1 = fmaf(v1.z, c4.z, lg1); lg1 = fmaf(v1.w, c4.w, lg1);
            const float4 v2 = a2[q];
            lg2 = fmaf(v2.x, c4.x, lg2); lg2 = fmaf(v2.y, c4.y, lg2);
            lg2 = fmaf(v2.z, c4.z, lg2); lg2 = fmaf(v2.w, c4.w, lg2);
            const float4 v3 = a3[q];
            lg3 = fmaf(v3.x, c4.x, lg3); lg3 = fmaf(v3.y, c4.y, lg3);
            lg3 = fmaf(v3.z, c4.z, lg3); lg3 = fmaf(v3.w, c4.w, lg3);
        }
        float lgs[4] = { lg0, lg1, lg2, lg3 };
#pragma unroll
        for (int j = 0; j < 4; j++) {
            float lg = lgs[j];
            float m = lg;
#pragma unroll
            for (int off = 16; off > 0; off >>= 1)
                m = fmaxf(m, __shfl_xor_sync(0xffffffffu, m, off));
            const float e = __expf(lg - m);
            float s = e;
#pragma unroll
            for (int off = 16; off > 0; off >>= 1)
                s += __shfl_xor_sync(0xffffffffu, s, off);
            sCoefT[lane*36 + t0 + j] = e / s;     // transposed: [n][token]
        }
    }
    __syncthreads();

    // ---- phase 4: A_mat + exp terms + half-chunk aggregates (float4 coeff reads) ----
    const int c = tid & 255;
    const int h = tid >> 8;
    const int rbase = h * 16;
    float am[16];
#pragma unroll
    for (int rr = 0; rr < 16; rr++) am[rr] = 0.f;
#pragma unroll 4
    for (int n = 0; n < 32; n++) {
        const float ab = g_Abasis[n*256 + c];
        const float4* cp = (const float4*)(sCoefT + n*36 + rbase);
#pragma unroll
        for (int j4 = 0; j4 < 4; j4++) {
            const float4 cc = cp[j4];
            am[j4*4+0] = fmaf(cc.x, ab, am[j4*4+0]);
            am[j4*4+1] = fmaf(cc.y, ab, am[j4*4+1]);
            am[j4*4+2] = fmaf(cc.z, ab, am[j4*4+2]);
            am[j4*4+3] = fmaf(cc.w, ab, am[j4*4+3]);
        }
    }
    float aAm = 1.f, bBm = 0.f, aAv = 1.f, bBv = 0.f;
    float* sAL2 = (float*)(smc + TBBASE);
#pragma unroll 4
    for (int rr = 0; rr < 16; rr++) {
        const int r = rbase + rr;
        const float a = am[rr];
        const float t = sT[r];
        const float eAm = __expf(a * t);
        const float inv = __fdividef(1.0f, a);
        const float al  = sAL2[r*256 + c];
        const float eBm = (eAm - 1.f) * inv * al;
        const float eAv = eAm * eAm;
        const float eBv = 0.5f*(eAv - 1.f)*inv + EPSF;
        const size_t o = (size_t)(tok0 + r)*256 + c;
        g_eAiv[o] = make_float2(eAm, inv);
        bBm = fmaf(eAm, bBm, eBm); aAm *= eAm;
        bBv = fmaf(eAv, bBv, eBv); aAv *= eAv;
    }
    float* sPar = (float*)smc;
    sPar[(h*4+0)*256 + c] = aAm;
    sPar[(h*4+1)*256 + c] = bBm;
    sPar[(h*4+2)*256 + c] = aAv;
    sPar[(h*4+3)*256 + c] = bBv;
    __syncthreads();
    if (tid < 256) {
        const float A0m = sPar[tid],        B0m = sPar[256 + tid];
        const float A0v = sPar[512 + tid],  B0v = sPar[768 + tid];
        const float A1m = sPar[1024 + tid], B1m = sPar[1280 + tid];
        const float A1v = sPar[1536 + tid], B1v = sPar[1792 + tid];
        g_aggA[bc*512 + tid]       = A1m * A0m;
        g_aggB[bc*512 + tid]       = fmaf(A1m, B0m, B1m);
        g_aggA[bc*512 + 256 + tid] = A1v * A0v;
        g_aggB[bc*512 + 256 + tid] = fmaf(A1v, B0v, B1v);
    }
}

// ---------------- scan over chunk aggregates (64 blocks x 128 threads) ----------------
__global__ void k_scan2() {
    const int b = blockIdx.x >> 2;
    const int c = (blockIdx.x & 3)*128 + threadIdx.x;
    float s = g_initmv[c];
#pragma unroll 4
    for (int j = 0; j < NCHUNK; j++) {
        const int idx = (b*NCHUNK + j)*512 + c;
        g_carry[idx] = s;
        s = fmaf(g_aggA[idx], s, g_aggB[idx]);
    }
}

// ---------------- k_fused: two-pass scan-apply + warp-mma output GEMMs ----------------
#define FBBASE   (4*ATILE)
#define SMEM_OUT (FBBASE + 2*BTILE)

__global__ void __launch_bounds__(512, 2) k_fused(const float* __restrict__ Z,
        const float* __restrict__ alphas,
        float* __restrict__ out_means, float* __restrict__ out_stds) {
    extern __shared__ char smc[];
    const uint32_t sbase = smem_u32(smc);
    const int tid = threadIdx.x;
    const int bc = blockIdx.x;
    const int tok0 = bc * 32;

    // ---- phase 1a: scan apply -> X (mean) and V (std) split tiles ----
    {
        const int d = tid & 255;
        if (tid < 256) {
            float s = g_carry[bc*512 + d];
#pragma unroll 4
            for (int r = 0; r < 32; r++) {
                const size_t o = (size_t)(tok0 + r)*256 + d;
                const float2 ei = g_eAiv[o];
                const float al = alphas[o];
                s = fmaf(ei.x, s, (ei.x - 1.f)*ei.y*al);
                put_split(smc, smc + ATILE, r, d, s);
            }
        } else {
            float s = g_carry[bc*512 + 256 + d];
            const float yv = g_yvar[d];
#pragma unroll 4
            for (int r = 0; r < 32; r++) {
                const size_t o = (size_t)(tok0 + r)*256 + d;
                const float2 ei = g_eAiv[o];
                const float eAv = ei.x * ei.x;
                s = fmaf(eAv, s, 0.5f*(eAv - 1.f)*ei.y + EPSF);
                put_split(smc + 2*ATILE, smc + 3*ATILE, r, d, sqrtf(s + yv));
            }
        }
    }

    const int lane = tid & 31, wid = tid >> 5;
    const int row0 = (wid & 1) * 16;
    const int col0 = (wid >> 1) * 32;
    float cm[4][4], cs[4][4];
#pragma unroll
    for (int nt = 0; nt < 4; nt++)
#pragma unroll
        for (int q = 0; q < 4; q++) { cm[nt][q] = 0.f; cs[nt][q] = 0.f; }

    const uint32_t aoff = sbase + (uint32_t)(row0 + (lane & 15))*ASTRIDE + (uint32_t)(lane >> 4)*16;
    const uint32_t boff = sbase + FBBASE + (uint32_t)(col0 + (lane & 15))*BSTRIDE + (uint32_t)(lane >> 4)*16;

    // ---- pass A: WME against X (means) and V (stds) ----
    for (int kc = 0; kc < 8; kc++) {
        __syncthreads();
#pragma unroll
        for (int m = 0; m < 2; m++) {
            const uint4* src = ((m == 0) ? (const uint4*)g_WMEh : (const uint4*)g_WMEl) + kc*1024;
            char* dst = smc + FBBASE + m*BTILE;
#pragma unroll
            for (int i = 0; i < 2; i++) {
                const int q = tid + i*512;
                const int f = q >> 2, seg = q & 3;
                *(uint4*)(dst + f*BSTRIDE + seg*16) = src[q];
            }
        }
        __syncthreads();
#pragma unroll
        for (int kk = 0; kk < 2; kk++) {
            const uint32_t ak = aoff + (uint32_t)(kc*64 + kk*32);
            uint32_t aXh[4], aXl[4], aVh[4], aVl[4];
            ldsm4(ak,           aXh[0], aXh[1], aXh[2], aXh[3]);
            ldsm4(ak + ATILE,   aXl[0], aXl[1], aXl[2], aXl[3]);
            ldsm4(ak + 2*ATILE, aVh[0], aVh[1], aVh[2], aVh[3]);
            ldsm4(ak + 3*ATILE, aVl[0], aVl[1], aVl[2], aVl[3]);
            uint32_t b[2][2][4];
            const uint32_t bk = boff + (uint32_t)(kk*32);
#pragma unroll
            for (int m = 0; m < 2; m++)
#pragma unroll
                for (int p = 0; p < 2; p++)
                    ldsm4(bk + m*BTILE + p*16*BSTRIDE,
                          b[m][p][0], b[m][p][1], b[m][p][2], b[m][p][3]);
#pragma unroll
            for (int nt = 0; nt < 4; nt++) {
                const int p = nt >> 1, s2 = nt & 1;
                const uint32_t bh0 = b[0][p][s2], bh1 = b[0][p][s2+2];
                const uint32_t bl0 = b[1][p][s2], bl1 = b[1][p][s2+2];
                mma_bf16(cm[nt], aXh, bh0, bh1);
                mma_bf16(cm[nt], aXh, bl0, bl1);
                mma_bf16(cm[nt], aXl, bh0, bh1);
                mma_bf16(cs[nt], aVh, bh0, bh1);
                mma_bf16(cs[nt], aVh, bl0, bl1);
                mma_bf16(cs[nt], aVl, bh0, bh1);
            }
        }
    }
    __syncthreads();

    // ---- phase 1b: H = Z -> tiles 0,1 (aliasing X), float4 ----
    {
#pragma unroll
        for (int it = 0; it < 4; it++) {
            const int q = tid + it*512;
            const int r = q >> 6, d4 = (q & 63) * 4;
            const float4 z4 = *(const float4*)(Z + (size_t)(tok0 + r)*256 + d4);
            put_split4(smc, smc + ATILE, r, d4, z4);
        }
    }

    // ---- pass B: WCE against H (means accumulate) ----
    for (int kc = 0; kc < 8; kc++) {
        __syncthreads();
#pragma unroll
        for (int m = 0; m < 2; m++) {
            const uint4* src = ((m == 0) ? (const uint4*)g_WCEh : (const uint4*)g_WCEl) + kc*1024;
            char* dst = smc + FBBASE + m*BTILE;
#pragma unroll
            for (int i = 0; i < 2; i++) {
                const int q = tid + i*512;
                const int f = q >> 2, seg = q & 3;
                *(uint4*)(dst + f*BSTRIDE + seg*16) = src[q];
            }
        }
        __syncthreads();
#pragma unroll
        for (int kk = 0; kk < 2; kk++) {
            const uint32_t ak = aoff + (uint32_t)(kc*64 + kk*32);
            uint32_t aHh[4], aHl[4];
            ldsm4(ak,         aHh[0], aHh[1], aHh[2], aHh[3]);
            ldsm4(ak + ATILE, aHl[0], aHl[1], aHl[2], aHl[3]);
            uint32_t b[2][2][4];
            const uint32_t bk = boff + (uint32_t)(kk*32);
#pragma unroll
            for (int m = 0; m < 2; m++)
#pragma unroll
                for (int p = 0; p < 2; p++)
                    ldsm4(bk + m*BTILE + p*16*BSTRIDE,
                          b[m][p][0], b[m][p][1], b[m][p][2], b[m][p][3]);
#pragma unroll
            for (int nt = 0; nt < 4; nt++) {
                const int p = nt >> 1, s2 = nt & 1;
                const uint32_t bh0 = b[0][p][s2], bh1 = b[0][p][s2+2];
                const uint32_t bl0 = b[1][p][s2], bl1 = b[1][p][s2+2];
                mma_bf16(cm[nt], aHh, bh0, bh1);
                mma_bf16(cm[nt], aHh, bl0, bl1);
                mma_bf16(cm[nt], aHl, bh0, bh1);
            }
        }
    }

    // ---- epilogue ----
    const int r1 = lane >> 2, c2o = (lane & 3)*2;
    const int grow = tok0 + row0 + r1;
#pragma unroll
    for (int nt = 0; nt < 4; nt++) {
        const int col = col0 + nt*8 + c2o;
        const size_t o0 = (size_t)grow*256 + col;
        const size_t o1 = (size_t)(grow + 8)*256 + col;
        *(float2*)(out_means + o0) = make_float2(cm[nt][0], cm[nt][1]);
        *(float2*)(out_means + o1) = make_float2(cm[nt][2], cm[nt][3]);
        *(float2*)(out_stds  + o0) = make_float2(cs[nt][0], cs[nt][1]);
        *(float2*)(out_stds  + o1) = make_float2(cs[nt][2], cs[nt][3]);
    }
}

// ---------------- launch ----------------
extern "C" void kernel_launch(void* const* d_in, const int* in_sizes, int n_in,
                              void* d_out, int out_size) {
    const float* Z   = (const float*)d_in[0];
    const float* obs = (const float*)d_in[1];
    const float* D   = (const float*)d_in[2];
    const float* cW  = (const float*)d_in[3];
    const float* cb  = (const float*)d_in[4];
    const float* E_w = (const float*)d_in[5];
    const float* B_w = (const float*)d_in[6];
    const float* C_w = (const float*)d_in[7];
    const float* M_w = (const float*)d_in[8];
    const float* imp = (const float*)d_in[9];
    const float* ilv = (const float*)d_in[10];
    const float* ylv = (const float*)d_in[11];

    float* out        = (float*)d_out;
    float* out_means  = out;
    float* out_stds   = out + (size_t)BTn * LDn;
    float* out_alphas = out + 2 * (size_t)BTn * LDn;

    cudaFuncSetAttribute(k_token, cudaFuncAttributeMaxDynamicSharedMemorySize, SMEM_TOKEN);
    cudaFuncSetAttribute(k_fused, cudaFuncAttributeMaxDynamicSharedMemorySize, SMEM_OUT);

    k_pre_misc<<<320, 256>>>(E_w, D, imp, ilv, ylv, B_w);
    k_pre_gemm<<<dim3(8,8,2), dim3(32,32)>>>(E_w, M_w, C_w);
    k_token<<<BTn/32, 512, SMEM_TOKEN>>>(Z, obs, cW, cb, out_alphas);
    k_scan2<<<64, 128>>>();
    k_fused<<<BTn/32, 512, SMEM_OUT>>>(Z, out_alphas, out_means, out_stds);
}

// round 13
// speedup vs baseline: 1.9161x; 1.0802x over previous
#include <cuda_runtime.h>
#include <cuda_bf16.h>
#include <math.h>
#include <stdint.h>

#define EPSF 1e-6f
#define Bn 16
#define Tn 2048
#define LDn 256
#define NBn 32
#define BTn (Bn*Tn)
#define NCHUNK 64

typedef unsigned long long ull;

// ---------- warp-mma helpers ----------
static __device__ __forceinline__ uint32_t smem_u32(const void* p) {
    uint32_t a;
    asm("{ .reg .u64 t; cvta.to.shared.u64 t, %1; cvt.u32.u64 %0, t; }" : "=r"(a) : "l"(p));
    return a;
}
__device__ __forceinline__ void ldsm4(uint32_t addr, uint32_t& r0, uint32_t& r1,
                                      uint32_t& r2, uint32_t& r3) {
    asm volatile("ldmatrix.sync.aligned.m8n8.x4.shared.b16 {%0,%1,%2,%3}, [%4];"
                 : "=r"(r0), "=r"(r1), "=r"(r2), "=r"(r3) : "r"(addr));
}
__device__ __forceinline__ void mma_bf16(float* c, const uint32_t* a, uint32_t b0, uint32_t b1) {
    asm volatile(
        "mma.sync.aligned.m16n8k16.row.col.f32.bf16.bf16.f32 "
        "{%0,%1,%2,%3},{%4,%5,%6,%7},{%8,%9},{%0,%1,%2,%3};"
        : "+f"(c[0]), "+f"(c[1]), "+f"(c[2]), "+f"(c[3])
        : "r"(a[0]), "r"(a[1]), "r"(a[2]), "r"(a[3]), "r"(b0), "r"(b1));
}

// -------- scratch (device globals) --------
__device__ float2 g_eAiv[(size_t)BTn*LDn];   // (exp(A t), 1/A) packed
__device__ float g_aggA[Bn*NCHUNK*512];
__device__ float g_aggB[Bn*NCHUNK*512];
__device__ float g_carry[Bn*NCHUNK*512];
__device__ float g_Abasis[NBn*LDn];
__device__ float g_initmv[512];
__device__ float g_yvar[LDn];
// bf16 split weights, layout [kchunk(8)][row(256)][k(32)] per matrix
__device__ __align__(16) __nv_bfloat16 g_WMEh[65536];
__device__ __align__(16) __nv_bfloat16 g_WMEl[65536];
__device__ __align__(16) __nv_bfloat16 g_WCEh[65536];
__device__ __align__(16) __nv_bfloat16 g_WCEl[65536];
__device__ __align__(16) __nv_bfloat16 g_Bwh[65536];
__device__ __align__(16) __nv_bfloat16 g_Bwl[65536];

// ---------------- precompute: vectors + A_basis + B_w split (merged) ----------------
__global__ void k_pre_misc(const float* __restrict__ E_w, const float* __restrict__ D,
                           const float* __restrict__ imp, const float* __restrict__ ilv,
                           const float* __restrict__ ylv, const float* __restrict__ B_w) {
    const int tid = threadIdx.x;
    if (blockIdx.x < 64) {
        const int lane = tid & 31;
        const int w = blockIdx.x*8 + (tid >> 5);
        float s = 0.f;
        if (w < 256) {
#pragma unroll
            for (int j = 0; j < 8; j++) { int k = lane + 32*j; s = fmaf(E_w[k*256 + w], imp[k], s); }
        } else {
            const int i = w - 256;
#pragma unroll
            for (int j = 0; j < 8; j++) {
                int k = lane + 32*j; float e = E_w[k*256 + i];
                s = fmaf(e*e, expf(ilv[k]) + EPSF, s);
            }
        }
#pragma unroll
        for (int off = 16; off > 0; off >>= 1) s += __shfl_xor_sync(0xffffffffu, s, off);
        if (lane == 0) {
            g_initmv[w] = s;
            if (w < 256) g_yvar[w] = expf(ylv[w]) + EPSF;
        }
        const int gid = blockIdx.x*256 + tid;
        if (gid < NBn*LDn) g_Abasis[gid] = -(expf(D[gid]) + EPSF);
    } else {
        const int e = blockIdx.x - 64, d = tid;
        const float v = B_w[e*256 + d];
        __nv_bfloat16 h = __float2bfloat16(v);
        __nv_bfloat16 l = __float2bfloat16(v - __bfloat162float(h));
        const int idx = (d >> 5)*8192 + e*32 + (d & 31);
        g_Bwh[idx] = h;
        g_Bwl[idx] = l;
    }
}

// ---------------- precompute: W_ME/W_CE bf16 splits, [kc][f][kk] ----------------
__global__ void k_pre_gemm(const float* __restrict__ E_w, const float* __restrict__ M_w,
                           const float* __restrict__ C_w) {
    const float* X = (blockIdx.z == 0) ? M_w : C_w;
    __nv_bfloat16* oh = (blockIdx.z == 0) ? g_WMEh : g_WCEh;
    __nv_bfloat16* ol = (blockIdx.z == 0) ? g_WMEl : g_WCEl;
    __shared__ float sE[32][33];
    __shared__ float sX[32][33];
    const int tx = threadIdx.x, ty = threadIdx.y;
    const int d0 = blockIdx.x*32, f0 = blockIdx.y*32;
    float acc = 0.f;
    for (int e0 = 0; e0 < 256; e0 += 32) {
        sE[ty][tx] = E_w[(e0+ty)*256 + d0 + tx];
        sX[ty][tx] = X[(f0+ty)*256 + e0 + tx];
        __syncthreads();
#pragma unroll
        for (int e = 0; e < 32; e++) acc = fmaf(sE[e][ty], sX[tx][e], acc);
        __syncthreads();
    }
    const int f = f0 + tx, d = d0 + ty;
    __nv_bfloat16 h = __float2bfloat16(acc);
    __nv_bfloat16 l = __float2bfloat16(acc - __bfloat162float(h));
    const int idx = (d >> 5)*8192 + f*32 + (d & 31);
    oh[idx] = h;
    ol[idx] = l;
}

// ---------------- shared tile geometry ----------------
#define ASTRIDE 528
#define ATILE   16896
#define BSTRIDE 80
#define BTILE   20480

__device__ __forceinline__ void put_split(char* hB, char* lB, int r, int d, float v) {
    __nv_bfloat16 h = __float2bfloat16(v);
    __nv_bfloat16 l = __float2bfloat16(v - __bfloat162float(h));
    const uint32_t off = (uint32_t)r*ASTRIDE + (uint32_t)d*2;
    *(__nv_bfloat16*)(hB + off) = h;
    *(__nv_bfloat16*)(lB + off) = l;
}

// vectorized: 4 consecutive d's, one 8B store per tile
__device__ __forceinline__ void put_split4(char* hB, char* lB, int r, int d4, float4 v) {
    ull hp = 0, lp = 0;
    const float vv[4] = { v.x, v.y, v.z, v.w };
#pragma unroll
    for (int j = 0; j < 4; j++) {
        __nv_bfloat16 h = __float2bfloat16(vv[j]);
        __nv_bfloat16 l = __float2bfloat16(vv[j] - __bfloat162float(h));
        hp |= (ull)__bfloat16_as_ushort(h) << (16*j);
        lp |= (ull)__bfloat16_as_ushort(l) << (16*j);
    }
    const uint32_t off = (uint32_t)r*ASTRIDE + (uint32_t)d4*2;
    *(ull*)(hB + off) = hp;
    *(ull*)(lB + off) = lp;
}

// ---------------- k_token ----------------
// A area [0, 33792): Z hi/lo tiles; later sCW (32x260 f32 = 33280) then sPar (8x256 f32)
// B area [33792, 74752): B staging hi/lo; later sAL (32x256 f32)
// sCoefT at 74752 (32n x 36 f32 = 4608), sT at 79360
#define TBBASE   33792
#define TCOEF    74752
#define TTIME    79360
#define SMEM_TOKEN (TTIME + 128)
__global__ void __launch_bounds__(512, 2) k_token(const float* __restrict__ Z,
        const float* __restrict__ obs, const float* __restrict__ cW,
        const float* __restrict__ cb, float* __restrict__ alphas_out) {
    extern __shared__ char smc[];
    const uint32_t sbase = smem_u32(smc);
    float* sCoefT = (float*)(smc + TCOEF);
    float* sT     = (float*)(smc + TTIME);
    const int tid = threadIdx.x;
    const int bc = blockIdx.x;
    const int tok0 = bc * 32;

    // ---- phase 1: Z -> bf16 split tiles (float4 / 8B stores) ----
    {
#pragma unroll
        for (int it = 0; it < 4; it++) {
            const int q = tid + it*512;          // 0..2047 = 32 r x 64 d4
            const int r = q >> 6, d4 = (q & 63) * 4;
            const float4 z4 = *(const float4*)(Z + (size_t)(tok0 + r)*256 + d4);
            put_split4(smc, smc + ATILE, r, d4, z4);
        }
        if (tid < 32) sT[tid] = obs[tok0 + tid];
    }

    // ---- phase 2: alphas = Z @ B_w^T via 3-term split mma ----
    const int lane = tid & 31, wid = tid >> 5;
    const int row0 = (wid & 1) * 16;
    const int col0 = (wid >> 1) * 32;
    float cm[4][4];
#pragma unroll
    for (int nt = 0; nt < 4; nt++)
#pragma unroll
        for (int q = 0; q < 4; q++) cm[nt][q] = 0.f;

    const uint32_t aoff = sbase + (uint32_t)(row0 + (lane & 15))*ASTRIDE + (uint32_t)(lane >> 4)*16;
    const uint32_t boff = sbase + TBBASE + (uint32_t)(col0 + (lane & 15))*BSTRIDE + (uint32_t)(lane >> 4)*16;

    for (int kc = 0; kc < 8; kc++) {
        __syncthreads();
#pragma unroll
        for (int m = 0; m < 2; m++) {
            const uint4* src = ((m == 0) ? (const uint4*)g_Bwh : (const uint4*)g_Bwl) + kc*1024;
            char* dst = smc + TBBASE + m*BTILE;
#pragma unroll
            for (int i = 0; i < 2; i++) {
                const int q = tid + i*512;
                const int f = q >> 2, seg = q & 3;
                *(uint4*)(dst + f*BSTRIDE + seg*16) = src[q];
            }
        }
        __syncthreads();
#pragma unroll
        for (int kk = 0; kk < 2; kk++) {
            const uint32_t ak = aoff + (uint32_t)(kc*64 + kk*32);
            uint32_t aZh[4], aZl[4];
            ldsm4(ak,         aZh[0], aZh[1], aZh[2], aZh[3]);
            ldsm4(ak + ATILE, aZl[0], aZl[1], aZl[2], aZl[3]);
            uint32_t b[2][2][4];
            const uint32_t bk = boff + (uint32_t)(kk*32);
#pragma unroll
            for (int m = 0; m < 2; m++)
#pragma unroll
                for (int p = 0; p < 2; p++)
                    ldsm4(bk + m*BTILE + p*16*BSTRIDE,
                          b[m][p][0], b[m][p][1], b[m][p][2], b[m][p][3]);
#pragma unroll
            for (int nt = 0; nt < 4; nt++) {
                const int p = nt >> 1, s2 = nt & 1;
                const uint32_t bh0 = b[0][p][s2], bh1 = b[0][p][s2+2];
                const uint32_t bl0 = b[1][p][s2], bl1 = b[1][p][s2+2];
                mma_bf16(cm[nt], aZh, bh0, bh1);
                mma_bf16(cm[nt], aZh, bl0, bl1);
                mma_bf16(cm[nt], aZl, bh0, bh1);
            }
        }
    }
    __syncthreads();

    // ---- epilogue: alphas -> sAL (B area) + gmem; cW -> sCW (A area, pad 260) ----
    float* sAL = (float*)(smc + TBBASE);
    float* sCW = (float*)smc;
    {
        const int r1 = lane >> 2, c2o = (lane & 3)*2;
#pragma unroll
        for (int nt = 0; nt < 4; nt++) {
            const int col = col0 + nt*8 + c2o;
            const int lr0 = row0 + r1, lr1 = row0 + r1 + 8;
            sAL[lr0*256 + col]     = cm[nt][0];
            sAL[lr0*256 + col + 1] = cm[nt][1];
            sAL[lr1*256 + col]     = cm[nt][2];
            sAL[lr1*256 + col + 1] = cm[nt][3];
            *(float2*)(alphas_out + (size_t)(tok0+lr0)*256 + col) = make_float2(cm[nt][0], cm[nt][1]);
            *(float2*)(alphas_out + (size_t)(tok0+lr1)*256 + col) = make_float2(cm[nt][2], cm[nt][3]);
        }
        for (int idx = tid; idx < 32*256; idx += 512)
            sCW[(idx >> 8)*260 + (idx & 255)] = cW[idx];
    }
    __syncthreads();

    // ---- phase 3: logits + softmax (8 warps x 4 tokens, lane = basis n) ----
    if (wid < 8) {
        const int t0 = wid * 4;
        const float4* crow = (const float4*)(sCW + lane*260);
        const float4* a0 = (const float4*)(sAL + (t0+0)*256);
        const float4* a1 = (const float4*)(sAL + (t0+1)*256);
        const float4* a2 = (const float4*)(sAL + (t0+2)*256);
        const float4* a3 = (const float4*)(sAL + (t0+3)*256);
        const float bias = cb[lane];
        float lg0 = bias, lg1 = bias, lg2 = bias, lg3 = bias;
#pragma unroll 4
        for (int q = 0; q < 64; q++) {
            const float4 c4 = crow[q];
            const float4 v0 = a0[q];
            lg0 = fmaf(v0.x, c4.x, lg0); lg0 = fmaf(v0.y, c4.y, lg0);
            lg0 = fmaf(v0.z, c4.z, lg0); lg0 = fmaf(v0.w, c4.w, lg0);
            const float4 v1 = a1[q];
            lg1 = fmaf(v1.x, c4.x, lg1); lg1 = fmaf(v1.y, c4.y, lg1);
            lg1 = fmaf(v1.z, c4.z, lg1); lg1 = fmaf(v1.w, c4.w, lg1);
            const float4 v2 = a2[q];
            lg2 = fmaf(v2.x, c4.x, lg2); lg2 = fmaf(v2.y, c4.y, lg2);
            lg2 = fmaf(v2.z, c4.z, lg2); lg2 = fmaf(v2.w, c4.w, lg2);
            const float4 v3 = a3[q];
            lg3 = fmaf(v3.x, c4.x, lg3); lg3 = fmaf(v3.y, c4.y, lg3);
            lg3 = fmaf(v3.z, c4.z, lg3); lg3 = fmaf(v3.w, c4.w, lg3);
        }
        float lgs[4] = { lg0, lg1, lg2, lg3 };
#pragma unroll
        for (int j = 0; j < 4; j++) {
            float lg = lgs[j];
            float m = lg;
#pragma unroll
            for (int off = 16; off > 0; off >>= 1)
                m = fmaxf(m, __shfl_xor_sync(0xffffffffu, m, off));
            const float e = __expf(lg - m);
            float s = e;
#pragma unroll
            for (int off = 16; off > 0; off >>= 1)
                s += __shfl_xor_sync(0xffffffffu, s, off);
            sCoefT[lane*36 + t0 + j] = e / s;     // transposed: [n][token]
        }
    }
    __syncthreads();

    // ---- phase 4: A_mat + exp terms + half-chunk aggregates (float4 coeff reads) ----
    const int c = tid & 255;
    const int h = tid >> 8;
    const int rbase = h * 16;
    float am[16];
#pragma unroll
    for (int rr = 0; rr < 16; rr++) am[rr] = 0.f;
#pragma unroll 4
    for (int n = 0; n < 32; n++) {
        const float ab = g_Abasis[n*256 + c];
        const float4* cp = (const float4*)(sCoefT + n*36 + rbase);
#pragma unroll
        for (int j4 = 0; j4 < 4; j4++) {
            const float4 cc = cp[j4];
            am[j4*4+0] = fmaf(cc.x, ab, am[j4*4+0]);
            am[j4*4+1] = fmaf(cc.y, ab, am[j4*4+1]);
            am[j4*4+2] = fmaf(cc.z, ab, am[j4*4+2]);
            am[j4*4+3] = fmaf(cc.w, ab, am[j4*4+3]);
        }
    }
    float aAm = 1.f, bBm = 0.f, aAv = 1.f, bBv = 0.f;
    float* sAL2 = (float*)(smc + TBBASE);
#pragma unroll 4
    for (int rr = 0; rr < 16; rr++) {
        const int r = rbase + rr;
        const float a = am[rr];
        const float t = sT[r];
        const float eAm = __expf(a * t);
        const float inv = __fdividef(1.0f, a);
        const float al  = sAL2[r*256 + c];
        const float eBm = (eAm - 1.f) * inv * al;
        const float eAv = eAm * eAm;
        const float eBv = 0.5f*(eAv - 1.f)*inv + EPSF;
        const size_t o = (size_t)(tok0 + r)*256 + c;
        g_eAiv[o] = make_float2(eAm, inv);
        bBm = fmaf(eAm, bBm, eBm); aAm *= eAm;
        bBv = fmaf(eAv, bBv, eBv); aAv *= eAv;
    }
    float* sPar = (float*)smc;
    sPar[(h*4+0)*256 + c] = aAm;
    sPar[(h*4+1)*256 + c] = bBm;
    sPar[(h*4+2)*256 + c] = aAv;
    sPar[(h*4+3)*256 + c] = bBv;
    __syncthreads();
    if (tid < 256) {
        const float A0m = sPar[tid],        B0m = sPar[256 + tid];
        const float A0v = sPar[512 + tid],  B0v = sPar[768 + tid];
        const float A1m = sPar[1024 + tid], B1m = sPar[1280 + tid];
        const float A1v = sPar[1536 + tid], B1v = sPar[1792 + tid];
        g_aggA[bc*512 + tid]       = A1m * A0m;
        g_aggB[bc*512 + tid]       = fmaf(A1m, B0m, B1m);
        g_aggA[bc*512 + 256 + tid] = A1v * A0v;
        g_aggB[bc*512 + 256 + tid] = fmaf(A1v, B0v, B1v);
    }
}

// ---------------- warp-parallel scan over chunk aggregates ----------------
// One warp per (b, channel). Lane l handles chunks 2l, 2l+1; Kogge-Stone on
// the affine monoid (A,B): apply-prev-first compose (A,B)<-(A*Ap, B + A*Bp).
__global__ void __launch_bounds__(512) k_scan2() {
    const int gw = blockIdx.x*16 + (threadIdx.x >> 5);   // 0..8191
    const int b = gw >> 9;
    const int c = gw & 511;
    const int lane = threadIdx.x & 31;
    const int base = b*NCHUNK*512 + c;
    const int j0 = 2*lane;

    const float A0 = g_aggA[base + j0*512],     B0 = g_aggB[base + j0*512];
    const float A1 = g_aggA[base + (j0+1)*512], B1 = g_aggB[base + (j0+1)*512];
    const float init = g_initmv[c];

    // local compose: chunk j0 then j0+1
    float Ac = A1 * A0;
    float Bc = fmaf(A1, B0, B1);
    // inclusive Kogge-Stone scan (non-commutative; prev applied first)
#pragma unroll
    for (int off = 1; off < 32; off <<= 1) {
        const float Ap = __shfl_up_sync(0xffffffffu, Ac, off);
        const float Bp = __shfl_up_sync(0xffffffffu, Bc, off);
        if (lane >= off) {
            Bc = fmaf(Ac, Bp, Bc);
            Ac = Ac * Ap;
        }
    }
    // exclusive prefix = inclusive of lane-1 (identity at lane 0)
    float Aex = __shfl_up_sync(0xffffffffu, Ac, 1);
    float Bex = __shfl_up_sync(0xffffffffu, Bc, 1);
    if (lane == 0) { Aex = 1.f; Bex = 0.f; }

    const float s0 = fmaf(Aex, init, Bex);      // state before chunk j0
    g_carry[base + j0*512]     = s0;
    g_carry[base + (j0+1)*512] = fmaf(A0, s0, B0);
}

// ---------------- k_fused: two-pass scan-apply + warp-mma output GEMMs ----------------
#define FBBASE   (4*ATILE)
#define SMEM_OUT (FBBASE + 2*BTILE)

__global__ void __launch_bounds__(512, 2) k_fused(const float* __restrict__ Z,
        const float* __restrict__ alphas,
        float* __restrict__ out_means, float* __restrict__ out_stds) {
    extern __shared__ char smc[];
    const uint32_t sbase = smem_u32(smc);
    const int tid = threadIdx.x;
    const int bc = blockIdx.x;
    const int tok0 = bc * 32;

    // ---- phase 1a: scan apply -> X (mean) and V (std) split tiles ----
    {
        const int d = tid & 255;
        if (tid < 256) {
            float s = g_carry[bc*512 + d];
#pragma unroll 4
            for (int r = 0; r < 32; r++) {
                const size_t o = (size_t)(tok0 + r)*256 + d;
                const float2 ei = g_eAiv[o];
                const float al = alphas[o];
                s = fmaf(ei.x, s, (ei.x - 1.f)*ei.y*al);
                put_split(smc, smc + ATILE, r, d, s);
            }
        } else {
            float s = g_carry[bc*512 + 256 + d];
            const float yv = g_yvar[d];
#pragma unroll 4
            for (int r = 0; r < 32; r++) {
                const size_t o = (size_t)(tok0 + r)*256 + d;
                const float2 ei = g_eAiv[o];
                const float eAv = ei.x * ei.x;
                s = fmaf(eAv, s, 0.5f*(eAv - 1.f)*ei.y + EPSF);
                put_split(smc + 2*ATILE, smc + 3*ATILE, r, d, sqrtf(s + yv));
            }
        }
    }

    const int lane = tid & 31, wid = tid >> 5;
    const int row0 = (wid & 1) * 16;
    const int col0 = (wid >> 1) * 32;
    float cm[4][4], cs[4][4];
#pragma unroll
    for (int nt = 0; nt < 4; nt++)
#pragma unroll
        for (int q = 0; q < 4; q++) { cm[nt][q] = 0.f; cs[nt][q] = 0.f; }

    const uint32_t aoff = sbase + (uint32_t)(row0 + (lane & 15))*ASTRIDE + (uint32_t)(lane >> 4)*16;
    const uint32_t boff = sbase + FBBASE + (uint32_t)(col0 + (lane & 15))*BSTRIDE + (uint32_t)(lane >> 4)*16;

    // ---- pass A: WME against X (means) and V (stds) ----
    for (int kc = 0; kc < 8; kc++) {
        __syncthreads();
#pragma unroll
        for (int m = 0; m < 2; m++) {
            const uint4* src = ((m == 0) ? (const uint4*)g_WMEh : (const uint4*)g_WMEl) + kc*1024;
            char* dst = smc + FBBASE + m*BTILE;
#pragma unroll
            for (int i = 0; i < 2; i++) {
                const int q = tid + i*512;
                const int f = q >> 2, seg = q & 3;
                *(uint4*)(dst + f*BSTRIDE + seg*16) = src[q];
            }
        }
        __syncthreads();
#pragma unroll
        for (int kk = 0; kk < 2; kk++) {
            const uint32_t ak = aoff + (uint32_t)(kc*64 + kk*32);
            uint32_t aXh[4], aXl[4], aVh[4], aVl[4];
            ldsm4(ak,           aXh[0], aXh[1], aXh[2], aXh[3]);
            ldsm4(ak + ATILE,   aXl[0], aXl[1], aXl[2], aXl[3]);
            ldsm4(ak + 2*ATILE, aVh[0], aVh[1], aVh[2], aVh[3]);
            ldsm4(ak + 3*ATILE, aVl[0], aVl[1], aVl[2], aVl[3]);
            uint32_t b[2][2][4];
            const uint32_t bk = boff + (uint32_t)(kk*32);
#pragma unroll
            for (int m = 0; m < 2; m++)
#pragma unroll
                for (int p = 0; p < 2; p++)
                    ldsm4(bk + m*BTILE + p*16*BSTRIDE,
                          b[m][p][0], b[m][p][1], b[m][p][2], b[m][p][3]);
#pragma unroll
            for (int nt = 0; nt < 4; nt++) {
                const int p = nt >> 1, s2 = nt & 1;
                const uint32_t bh0 = b[0][p][s2], bh1 = b[0][p][s2+2];
                const uint32_t bl0 = b[1][p][s2], bl1 = b[1][p][s2+2];
                mma_bf16(cm[nt], aXh, bh0, bh1);
                mma_bf16(cm[nt], aXh, bl0, bl1);
                mma_bf16(cm[nt], aXl, bh0, bh1);
                mma_bf16(cs[nt], aVh, bh0, bh1);
                mma_bf16(cs[nt], aVh, bl0, bl1);
                mma_bf16(cs[nt], aVl, bh0, bh1);
            }
        }
    }
    __syncthreads();

    // ---- phase 1b: H = Z -> tiles 0,1 (aliasing X), float4 ----
    {
#pragma unroll
        for (int it = 0; it < 4; it++) {
            const int q = tid + it*512;
            const int r = q >> 6, d4 = (q & 63) * 4;
            const float4 z4 = *(const float4*)(Z + (size_t)(tok0 + r)*256 + d4);
            put_split4(smc, smc + ATILE, r, d4, z4);
        }
    }

    // ---- pass B: WCE against H (means accumulate) ----
    for (int kc = 0; kc < 8; kc++) {
        __syncthreads();
#pragma unroll
        for (int m = 0; m < 2; m++) {
            const uint4* src = ((m == 0) ? (const uint4*)g_WCEh : (const uint4*)g_WCEl) + kc*1024;
            char* dst = smc + FBBASE + m*BTILE;
#pragma unroll
            for (int i = 0; i < 2; i++) {
                const int q = tid + i*512;
                const int f = q >> 2, seg = q & 3;
                *(uint4*)(dst + f*BSTRIDE + seg*16) = src[q];
            }
        }
        __syncthreads();
#pragma unroll
        for (int kk = 0; kk < 2; kk++) {
            const uint32_t ak = aoff + (uint32_t)(kc*64 + kk*32);
            uint32_t aHh[4], aHl[4];
            ldsm4(ak,         aHh[0], aHh[1], aHh[2], aHh[3]);
            ldsm4(ak + ATILE, aHl[0], aHl[1], aHl[2], aHl[3]);
            uint32_t b[2][2][4];
            const uint32_t bk = boff + (uint32_t)(kk*32);
#pragma unroll
            for (int m = 0; m < 2; m++)
#pragma unroll
                for (int p = 0; p < 2; p++)
                    ldsm4(bk + m*BTILE + p*16*BSTRIDE,
                          b[m][p][0], b[m][p][1], b[m][p][2], b[m][p][3]);
#pragma unroll
            for (int nt = 0; nt < 4; nt++) {
                const int p = nt >> 1, s2 = nt & 1;
                const uint32_t bh0 = b[0][p][s2], bh1 = b[0][p][s2+2];
                const uint32_t bl0 = b[1][p][s2], bl1 = b[1][p][s2+2];
                mma_bf16(cm[nt], aHh, bh0, bh1);
                mma_bf16(cm[nt], aHh, bl0, bl1);
                mma_bf16(cm[nt], aHl, bh0, bh1);
            }
        }
    }

    // ---- epilogue ----
    const int r1 = lane >> 2, c2o = (lane & 3)*2;
    const int grow = tok0 + row0 + r1;
#pragma unroll
    for (int nt = 0; nt < 4; nt++) {
        const int col = col0 + nt*8 + c2o;
        const size_t o0 = (size_t)grow*256 + col;
        const size_t o1 = (size_t)(grow + 8)*256 + col;
        *(float2*)(out_means + o0) = make_float2(cm[nt][0], cm[nt][1]);
        *(float2*)(out_means + o1) = make_float2(cm[nt][2], cm[nt][3]);
        *(float2*)(out_stds  + o0) = make_float2(cs[nt][0], cs[nt][1]);
        *(float2*)(out_stds  + o1) = make_float2(cs[nt][2], cs[nt][3]);
    }
}

// ---------------- launch ----------------
extern "C" void kernel_launch(void* const* d_in, const int* in_sizes, int n_in,
                              void* d_out, int out_size) {
    const float* Z   = (const float*)d_in[0];
    const float* obs = (const float*)d_in[1];
    const float* D   = (const float*)d_in[2];
    const float* cW  = (const float*)d_in[3];
    const float* cb  = (const float*)d_in[4];
    const float* E_w = (const float*)d_in[5];
    const float* B_w = (const float*)d_in[6];
    const float* C_w = (const float*)d_in[7];
    const float* M_w = (const float*)d_in[8];
    const float* imp = (const float*)d_in[9];
    const float* ilv = (const float*)d_in[10];
    const float* ylv = (const float*)d_in[11];

    float* out        = (float*)d_out;
    float* out_means  = out;
    float* out_stds   = out + (size_t)BTn * LDn;
    float* out_alphas = out + 2 * (size_t)BTn * LDn;

    cudaFuncSetAttribute(k_token, cudaFuncAttributeMaxDynamicSharedMemorySize, SMEM_TOKEN);
    cudaFuncSetAttribute(k_fused, cudaFuncAttributeMaxDynamicSharedMemorySize, SMEM_OUT);

    k_pre_misc<<<320, 256>>>(E_w, D, imp, ilv, ylv, B_w);
    k_pre_gemm<<<dim3(8,8,2), dim3(32,32)>>>(E_w, M_w, C_w);
    k_token<<<BTn/32, 512, SMEM_TOKEN>>>(Z, obs, cW, cb, out_alphas);
    k_scan2<<<512, 512>>>();
    k_fused<<<BTn/32, 512, SMEM_OUT>>>(Z, out_alphas, out_means, out_stds);
}